// round 1
// baseline (speedup 1.0000x reference)
#include <cuda_runtime.h>
#include <math.h>

// Problem constants
#define BB 2
#define SS 1024
#define DD 512
#define HH 8
#define NEG_INF -1e30f

// Scratch (device globals; allocation is forbidden)
__device__ float g_Q[HH*BB*SS*DD];    // 32 MB, layout [h][b][s][d]
__device__ float g_K[HH*BB*SS*DD];
__device__ float g_V[HH*BB*SS*DD];
__device__ float g_E[HH*BB*SS*SS];    // 64 MB, layout [hb][s][t]
__device__ float g_XP[BB*SS*DD];      // 4 MB
__device__ int   g_mask[SS];

// ---------------------------------------------------------------------------
// Mask dtype normalization. The harness may deliver the boolean mask as
// uint8/bool, int32, or float32. We only read the FIRST 1024 bytes for
// detection (in-bounds for any element size >= 1 byte, since n=1024).
//   uint8:  b[4t] often nonzero AND upper bytes (b[4t+1..3]) often nonzero
//   int32:  upper bytes always zero
//   float32: b[4t] always zero (1.0f = 00 00 80 3f), upper bytes nonzero
// ---------------------------------------------------------------------------
__global__ void normalize_mask_kernel(const unsigned char* __restrict__ raw, int n) {
    __shared__ int s_c0, s_chi;
    if (threadIdx.x == 0) { s_c0 = 0; s_chi = 0; }
    __syncthreads();
    int c0 = 0, chi = 0;
    for (int t = threadIdx.x; t < 256; t += blockDim.x) {
        unsigned char b0 = raw[4*t], b1 = raw[4*t+1], b2 = raw[4*t+2], b3 = raw[4*t+3];
        if (b0) c0++;
        if (b1 | b2 | b3) chi++;
    }
    atomicAdd(&s_c0, c0);
    atomicAdd(&s_chi, chi);
    __syncthreads();
    int mode;                 // 0 = uint8, 1 = int32, 2 = float32
    if (s_chi == 0)      mode = 1;
    else if (s_c0 == 0)  mode = 2;
    else                 mode = 0;
    for (int t = threadIdx.x; t < n; t += blockDim.x) {
        int v;
        if (mode == 0)      v = (raw[t] != 0);
        else if (mode == 1) v = (((const int*)raw)[t] != 0);
        else                v = (((const float*)raw)[t] != 0.0f);
        g_mask[t] = v;
    }
}

// ---------------------------------------------------------------------------
// GEMM tile config: 128x64 block tile, BK=16, 256 threads, 8x4 microtile.
// Shared padded to avoid >2-way bank conflicts while keeping float4 alignment.
// ---------------------------------------------------------------------------

// NN: C[M,N] = A[M,K] @ B[K,N] (+bias). head_major remaps output cols to
// [h][b*s][d] layout (h = col>>9, d = col&511, B*S = 2048 rows).
__global__ void gemm_nn_kernel(const float* __restrict__ A, const float* __restrict__ B,
                               const float* __restrict__ bias, float* __restrict__ C,
                               int M, int N, int K, int head_major)
{
    __shared__ float As[16][132];
    __shared__ float Bs[16][68];
    const int tid = threadIdx.x;
    const int tx = tid & 15, ty = tid >> 4;
    const int bm0 = blockIdx.y * 128, bn0 = blockIdx.x * 64;

    float acc[8][4];
#pragma unroll
    for (int i = 0; i < 8; i++)
#pragma unroll
        for (int j = 0; j < 4; j++) acc[i][j] = 0.f;

    for (int k0 = 0; k0 < K; k0 += 16) {
#pragma unroll
        for (int p = 0; p < 2; p++) {
            int r = (tid >> 2) + p * 64;
            int c = (tid & 3) * 4;
            float4 v = *reinterpret_cast<const float4*>(A + (size_t)(bm0 + r) * K + k0 + c);
            As[c+0][r] = v.x; As[c+1][r] = v.y; As[c+2][r] = v.z; As[c+3][r] = v.w;
        }
        {
            int kk = tid >> 4, n4 = (tid & 15) * 4;
            *reinterpret_cast<float4*>(&Bs[kk][n4]) =
                *reinterpret_cast<const float4*>(B + (size_t)(k0 + kk) * N + bn0 + n4);
        }
        __syncthreads();
#pragma unroll
        for (int kk = 0; kk < 16; kk++) {
            float4 b4 = *reinterpret_cast<const float4*>(&Bs[kk][tx * 4]);
            float4 a0 = *reinterpret_cast<const float4*>(&As[kk][ty * 8]);
            float4 a1 = *reinterpret_cast<const float4*>(&As[kk][ty * 8 + 4]);
            float a[8] = {a0.x, a0.y, a0.z, a0.w, a1.x, a1.y, a1.z, a1.w};
            float b[4] = {b4.x, b4.y, b4.z, b4.w};
#pragma unroll
            for (int i = 0; i < 8; i++)
#pragma unroll
                for (int j = 0; j < 4; j++)
                    acc[i][j] += a[i] * b[j];
        }
        __syncthreads();
    }
#pragma unroll
    for (int i = 0; i < 8; i++) {
        int row = bm0 + ty * 8 + i;
#pragma unroll
        for (int j = 0; j < 4; j++) {
            int col = bn0 + tx * 4 + j;
            float v = acc[i][j];
            if (bias) v += bias[col];
            if (head_major) {
                int h = col >> 9, d = col & 511;
                C[((size_t)h * 2048 + row) * 512 + d] = v;
            } else {
                C[(size_t)row * N + col] = v;
            }
        }
    }
}

// NT: E[s,t] = sum_d Q[s,d]*K[t,d], then column mask. One (h,b) pair per z.
__global__ void energy_kernel(void)
{
    __shared__ float As[16][132];
    __shared__ float Bs[16][68];
    const int tid = threadIdx.x;
    const int tx = tid & 15, ty = tid >> 4;
    const int bm0 = blockIdx.y * 128, bn0 = blockIdx.x * 64;
    const int hb = blockIdx.z;
    const float* Aq = g_Q + (size_t)hb * SS * DD;
    const float* Bk = g_K + (size_t)hb * SS * DD;
    float* Ce = g_E + (size_t)hb * SS * SS;

    float acc[8][4];
#pragma unroll
    for (int i = 0; i < 8; i++)
#pragma unroll
        for (int j = 0; j < 4; j++) acc[i][j] = 0.f;

    for (int k0 = 0; k0 < DD; k0 += 16) {
#pragma unroll
        for (int p = 0; p < 2; p++) {
            int r = (tid >> 2) + p * 64;
            int c = (tid & 3) * 4;
            float4 v = *reinterpret_cast<const float4*>(Aq + (size_t)(bm0 + r) * DD + k0 + c);
            As[c+0][r] = v.x; As[c+1][r] = v.y; As[c+2][r] = v.z; As[c+3][r] = v.w;
        }
        {
            int r = tid >> 2;              // n-row within 64
            int c = (tid & 3) * 4;
            float4 v = *reinterpret_cast<const float4*>(Bk + (size_t)(bn0 + r) * DD + k0 + c);
            Bs[c+0][r] = v.x; Bs[c+1][r] = v.y; Bs[c+2][r] = v.z; Bs[c+3][r] = v.w;
        }
        __syncthreads();
#pragma unroll
        for (int kk = 0; kk < 16; kk++) {
            float4 b4 = *reinterpret_cast<const float4*>(&Bs[kk][tx * 4]);
            float4 a0 = *reinterpret_cast<const float4*>(&As[kk][ty * 8]);
            float4 a1 = *reinterpret_cast<const float4*>(&As[kk][ty * 8 + 4]);
            float a[8] = {a0.x, a0.y, a0.z, a0.w, a1.x, a1.y, a1.z, a1.w};
            float b[4] = {b4.x, b4.y, b4.z, b4.w};
#pragma unroll
            for (int i = 0; i < 8; i++)
#pragma unroll
                for (int j = 0; j < 4; j++)
                    acc[i][j] += a[i] * b[j];
        }
        __syncthreads();
    }
#pragma unroll
    for (int i = 0; i < 8; i++) {
        int row = bm0 + ty * 8 + i;
#pragma unroll
        for (int j = 0; j < 4; j++) {
            int col = bn0 + tx * 4 + j;
            float v = g_mask[col] ? acc[i][j] : NEG_INF;
            Ce[(size_t)row * SS + col] = v;
        }
    }
}

// Row softmax over 1024 columns; one block per row, 4 elems/thread.
__global__ void softmax_kernel(void)
{
    const size_t row = blockIdx.x;
    float* p = g_E + row * SS;
    const int t = threadIdx.x;
    float4 v = reinterpret_cast<float4*>(p)[t];

    float mx = fmaxf(fmaxf(v.x, v.y), fmaxf(v.z, v.w));
    __shared__ float red[8];
    __shared__ float s_max, s_sum;
#pragma unroll
    for (int off = 16; off > 0; off >>= 1)
        mx = fmaxf(mx, __shfl_xor_sync(0xffffffffu, mx, off));
    if ((t & 31) == 0) red[t >> 5] = mx;
    __syncthreads();
    if (t == 0) {
        float m = red[0];
#pragma unroll
        for (int i = 1; i < 8; i++) m = fmaxf(m, red[i]);
        s_max = m;
    }
    __syncthreads();
    const float m = s_max;

    float4 e;
    e.x = __expf(v.x - m); e.y = __expf(v.y - m);
    e.z = __expf(v.z - m); e.w = __expf(v.w - m);
    float s = e.x + e.y + e.z + e.w;
#pragma unroll
    for (int off = 16; off > 0; off >>= 1)
        s += __shfl_xor_sync(0xffffffffu, s, off);
    if ((t & 31) == 0) red[t >> 5] = s;
    __syncthreads();
    if (t == 0) {
        float ss = 0.f;
#pragma unroll
        for (int i = 0; i < 8; i++) ss += red[i];
        s_sum = ss;
    }
    __syncthreads();
    const float inv = 1.0f / s_sum;
    e.x *= inv; e.y *= inv; e.z *= inv; e.w *= inv;
    reinterpret_cast<float4*>(p)[t] = e;
}

// TN: O[t,d] = sum_s attn[s,t] * V[s,d], then gamma blend with xp.
__global__ void out_kernel(const float* __restrict__ gamma, float* __restrict__ out)
{
    __shared__ float As[16][132];
    __shared__ float Bs[16][68];
    const int tid = threadIdx.x;
    const int tx = tid & 15, ty = tid >> 4;
    const int bm0 = blockIdx.y * 128, bn0 = blockIdx.x * 64;
    const int hb = blockIdx.z;
    const int h = hb >> 1, b = hb & 1;
    const float* Aa = g_E + (size_t)hb * SS * SS;   // [s][t]
    const float* Bv = g_V + (size_t)hb * SS * DD;   // [s][d]

    float acc[8][4];
#pragma unroll
    for (int i = 0; i < 8; i++)
#pragma unroll
        for (int j = 0; j < 4; j++) acc[i][j] = 0.f;

    for (int k0 = 0; k0 < SS; k0 += 16) {
#pragma unroll
        for (int p = 0; p < 2; p++) {
            int kk = (tid >> 5) + p * 8;
            int m4 = (tid & 31) * 4;
            float4 v = *reinterpret_cast<const float4*>(Aa + (size_t)(k0 + kk) * SS + bm0 + m4);
            *reinterpret_cast<float4*>(&As[kk][m4]) = v;
        }
        {
            int kk = tid >> 4, n4 = (tid & 15) * 4;
            *reinterpret_cast<float4*>(&Bs[kk][n4]) =
                *reinterpret_cast<const float4*>(Bv + (size_t)(k0 + kk) * DD + bn0 + n4);
        }
        __syncthreads();
#pragma unroll
        for (int kk = 0; kk < 16; kk++) {
            float4 b4 = *reinterpret_cast<const float4*>(&Bs[kk][tx * 4]);
            float4 a0 = *reinterpret_cast<const float4*>(&As[kk][ty * 8]);
            float4 a1 = *reinterpret_cast<const float4*>(&As[kk][ty * 8 + 4]);
            float a[8] = {a0.x, a0.y, a0.z, a0.w, a1.x, a1.y, a1.z, a1.w};
            float b[4] = {b4.x, b4.y, b4.z, b4.w};
#pragma unroll
            for (int i = 0; i < 8; i++)
#pragma unroll
                for (int j = 0; j < 4; j++)
                    acc[i][j] += a[i] * b[j];
        }
        __syncthreads();
    }
    const float g = gamma[h];
    const float inv = 1.0f / (g + 1.0f);
#pragma unroll
    for (int i = 0; i < 8; i++) {
        int t = bm0 + ty * 8 + i;
#pragma unroll
        for (int j = 0; j < 4; j++) {
            int d = bn0 + tx * 4 + j;
            float res = (g * acc[i][j] + g_XP[((size_t)b * SS + t) * DD + d]) * inv;
            out[(((size_t)b * HH + h) * SS + t) * DD + d] = res;
        }
    }
}

extern "C" void kernel_launch(void* const* d_in, const int* in_sizes, int n_in,
                              void* d_out, int out_size)
{
    const float* x     = (const float*)d_in[0];
    const float* y     = (const float*)d_in[1];
    const float* Wq    = (const float*)d_in[2];
    const float* bq    = (const float*)d_in[3];
    const float* Wk    = (const float*)d_in[4];
    const float* bk    = (const float*)d_in[5];
    const float* Wv    = (const float*)d_in[6];
    const float* bv    = (const float*)d_in[7];
    const float* Wp    = (const float*)d_in[8];
    const float* gamma = (const float*)d_in[9];
    const unsigned char* mask_raw = (const unsigned char*)d_in[10];
    float* out = (float*)d_out;

    float *Qp, *Kp, *Vp, *XPp;
    cudaGetSymbolAddress((void**)&Qp,  g_Q);
    cudaGetSymbolAddress((void**)&Kp,  g_K);
    cudaGetSymbolAddress((void**)&Vp,  g_V);
    cudaGetSymbolAddress((void**)&XPp, g_XP);

    normalize_mask_kernel<<<1, 256>>>(mask_raw, SS);

    // Projections: M=2048, N=4096, K=512 (head-major outputs)
    gemm_nn_kernel<<<dim3(64, 16), 256>>>(x, Wq, bq, Qp, 2048, 4096, 512, 1);
    gemm_nn_kernel<<<dim3(64, 16), 256>>>(y, Wk, bk, Kp, 2048, 4096, 512, 1);
    gemm_nn_kernel<<<dim3(64, 16), 256>>>(y, Wv, bv, Vp, 2048, 4096, 512, 1);
    // xp = x @ Wp: M=2048, N=512, K=512
    gemm_nn_kernel<<<dim3(8, 16), 256>>>(x, Wp, nullptr, XPp, 2048, 512, 512, 0);

    // energy + mask: per (h,b): 1024x1024x512
    energy_kernel<<<dim3(16, 8, 16), 256>>>();
    // softmax over rows
    softmax_kernel<<<HH * BB * SS, 256>>>();
    // attn^T @ V + gamma blend
    out_kernel<<<dim3(8, 8, 16), 256>>>(gamma, out);
}

// round 2
// speedup vs baseline: 1.0009x; 1.0009x over previous
#include <cuda_runtime.h>
#include <math.h>

// Problem constants
#define BB 2
#define SS 1024
#define DD 512
#define HH 8
#define NEG_INF -1e30f

// Scratch (device globals; allocation is forbidden)
__device__ float g_Q[HH*BB*SS*DD];    // 32 MB, layout [h][b][s][d]
__device__ float g_K[HH*BB*SS*DD];
__device__ float g_V[HH*BB*SS*DD];
__device__ float g_E[HH*BB*SS*SS];    // 64 MB, layout [hb][s][t]
__device__ float g_XP[BB*SS*DD];      // 4 MB
__device__ int   g_mask[SS];

// ---------------------------------------------------------------------------
// Mask dtype normalization. The harness may deliver the boolean mask as
// uint8/bool, int32, or float32. We only read the FIRST 1024 bytes for
// detection (in-bounds for any element size >= 1 byte, since n=1024).
//   uint8:  b[4t] often nonzero AND upper bytes (b[4t+1..3]) often nonzero
//   int32:  upper bytes always zero
//   float32: b[4t] always zero (1.0f = 00 00 80 3f), upper bytes nonzero
// ---------------------------------------------------------------------------
__global__ void normalize_mask_kernel(const unsigned char* __restrict__ raw, int n) {
    __shared__ int s_c0, s_chi;
    if (threadIdx.x == 0) { s_c0 = 0; s_chi = 0; }
    __syncthreads();
    int c0 = 0, chi = 0;
    for (int t = threadIdx.x; t < 256; t += blockDim.x) {
        unsigned char b0 = raw[4*t], b1 = raw[4*t+1], b2 = raw[4*t+2], b3 = raw[4*t+3];
        if (b0) c0++;
        if (b1 | b2 | b3) chi++;
    }
    atomicAdd(&s_c0, c0);
    atomicAdd(&s_chi, chi);
    __syncthreads();
    int mode;                 // 0 = uint8, 1 = int32, 2 = float32
    if (s_chi == 0)      mode = 1;
    else if (s_c0 == 0)  mode = 2;
    else                 mode = 0;
    for (int t = threadIdx.x; t < n; t += blockDim.x) {
        int v;
        if (mode == 0)      v = (raw[t] != 0);
        else if (mode == 1) v = (((const int*)raw)[t] != 0);
        else                v = (((const float*)raw)[t] != 0.0f);
        g_mask[t] = v;
    }
}

// ---------------------------------------------------------------------------
// GEMM tile config: 128x64 block tile, BK=16, 256 threads, 8x4 microtile.
// Shared padded to avoid >2-way bank conflicts while keeping float4 alignment.
// ---------------------------------------------------------------------------

// NN: C[M,N] = A[M,K] @ B[K,N] (+bias). head_major remaps output cols to
// [h][b*s][d] layout (h = col>>9, d = col&511, B*S = 2048 rows).
__global__ void gemm_nn_kernel(const float* __restrict__ A, const float* __restrict__ B,
                               const float* __restrict__ bias, float* __restrict__ C,
                               int M, int N, int K, int head_major)
{
    __shared__ float As[16][132];
    __shared__ float Bs[16][68];
    const int tid = threadIdx.x;
    const int tx = tid & 15, ty = tid >> 4;
    const int bm0 = blockIdx.y * 128, bn0 = blockIdx.x * 64;

    float acc[8][4];
#pragma unroll
    for (int i = 0; i < 8; i++)
#pragma unroll
        for (int j = 0; j < 4; j++) acc[i][j] = 0.f;

    for (int k0 = 0; k0 < K; k0 += 16) {
#pragma unroll
        for (int p = 0; p < 2; p++) {
            int r = (tid >> 2) + p * 64;
            int c = (tid & 3) * 4;
            float4 v = *reinterpret_cast<const float4*>(A + (size_t)(bm0 + r) * K + k0 + c);
            As[c+0][r] = v.x; As[c+1][r] = v.y; As[c+2][r] = v.z; As[c+3][r] = v.w;
        }
        {
            int kk = tid >> 4, n4 = (tid & 15) * 4;
            *reinterpret_cast<float4*>(&Bs[kk][n4]) =
                *reinterpret_cast<const float4*>(B + (size_t)(k0 + kk) * N + bn0 + n4);
        }
        __syncthreads();
#pragma unroll
        for (int kk = 0; kk < 16; kk++) {
            float4 b4 = *reinterpret_cast<const float4*>(&Bs[kk][tx * 4]);
            float4 a0 = *reinterpret_cast<const float4*>(&As[kk][ty * 8]);
            float4 a1 = *reinterpret_cast<const float4*>(&As[kk][ty * 8 + 4]);
            float a[8] = {a0.x, a0.y, a0.z, a0.w, a1.x, a1.y, a1.z, a1.w};
            float b[4] = {b4.x, b4.y, b4.z, b4.w};
#pragma unroll
            for (int i = 0; i < 8; i++)
#pragma unroll
                for (int j = 0; j < 4; j++)
                    acc[i][j] += a[i] * b[j];
        }
        __syncthreads();
    }
#pragma unroll
    for (int i = 0; i < 8; i++) {
        int row = bm0 + ty * 8 + i;
#pragma unroll
        for (int j = 0; j < 4; j++) {
            int col = bn0 + tx * 4 + j;
            float v = acc[i][j];
            if (bias) v += bias[col];
            if (head_major) {
                int h = col >> 9, d = col & 511;
                C[((size_t)h * 2048 + row) * 512 + d] = v;
            } else {
                C[(size_t)row * N + col] = v;
            }
        }
    }
}

// NT: E[s,t] = sum_d Q[s,d]*K[t,d], then column mask. One (h,b) pair per z.
__global__ void energy_kernel(void)
{
    __shared__ float As[16][132];
    __shared__ float Bs[16][68];
    const int tid = threadIdx.x;
    const int tx = tid & 15, ty = tid >> 4;
    const int bm0 = blockIdx.y * 128, bn0 = blockIdx.x * 64;
    const int hb = blockIdx.z;
    const float* Aq = g_Q + (size_t)hb * SS * DD;
    const float* Bk = g_K + (size_t)hb * SS * DD;
    float* Ce = g_E + (size_t)hb * SS * SS;

    float acc[8][4];
#pragma unroll
    for (int i = 0; i < 8; i++)
#pragma unroll
        for (int j = 0; j < 4; j++) acc[i][j] = 0.f;

    for (int k0 = 0; k0 < DD; k0 += 16) {
#pragma unroll
        for (int p = 0; p < 2; p++) {
            int r = (tid >> 2) + p * 64;
            int c = (tid & 3) * 4;
            float4 v = *reinterpret_cast<const float4*>(Aq + (size_t)(bm0 + r) * DD + k0 + c);
            As[c+0][r] = v.x; As[c+1][r] = v.y; As[c+2][r] = v.z; As[c+3][r] = v.w;
        }
        {
            int r = tid >> 2;              // n-row within 64
            int c = (tid & 3) * 4;
            float4 v = *reinterpret_cast<const float4*>(Bk + (size_t)(bn0 + r) * DD + k0 + c);
            Bs[c+0][r] = v.x; Bs[c+1][r] = v.y; Bs[c+2][r] = v.z; Bs[c+3][r] = v.w;
        }
        __syncthreads();
#pragma unroll
        for (int kk = 0; kk < 16; kk++) {
            float4 b4 = *reinterpret_cast<const float4*>(&Bs[kk][tx * 4]);
            float4 a0 = *reinterpret_cast<const float4*>(&As[kk][ty * 8]);
            float4 a1 = *reinterpret_cast<const float4*>(&As[kk][ty * 8 + 4]);
            float a[8] = {a0.x, a0.y, a0.z, a0.w, a1.x, a1.y, a1.z, a1.w};
            float b[4] = {b4.x, b4.y, b4.z, b4.w};
#pragma unroll
            for (int i = 0; i < 8; i++)
#pragma unroll
                for (int j = 0; j < 4; j++)
                    acc[i][j] += a[i] * b[j];
        }
        __syncthreads();
    }
#pragma unroll
    for (int i = 0; i < 8; i++) {
        int row = bm0 + ty * 8 + i;
#pragma unroll
        for (int j = 0; j < 4; j++) {
            int col = bn0 + tx * 4 + j;
            float v = g_mask[col] ? acc[i][j] : NEG_INF;
            Ce[(size_t)row * SS + col] = v;
        }
    }
}

// Row softmax over 1024 columns; one block per row, 4 elems/thread.
__global__ void softmax_kernel(void)
{
    const size_t row = blockIdx.x;
    float* p = g_E + row * SS;
    const int t = threadIdx.x;
    float4 v = reinterpret_cast<float4*>(p)[t];

    float mx = fmaxf(fmaxf(v.x, v.y), fmaxf(v.z, v.w));
    __shared__ float red[8];
    __shared__ float s_max, s_sum;
#pragma unroll
    for (int off = 16; off > 0; off >>= 1)
        mx = fmaxf(mx, __shfl_xor_sync(0xffffffffu, mx, off));
    if ((t & 31) == 0) red[t >> 5] = mx;
    __syncthreads();
    if (t == 0) {
        float m = red[0];
#pragma unroll
        for (int i = 1; i < 8; i++) m = fmaxf(m, red[i]);
        s_max = m;
    }
    __syncthreads();
    const float m = s_max;

    float4 e;
    e.x = __expf(v.x - m); e.y = __expf(v.y - m);
    e.z = __expf(v.z - m); e.w = __expf(v.w - m);
    float s = e.x + e.y + e.z + e.w;
#pragma unroll
    for (int off = 16; off > 0; off >>= 1)
        s += __shfl_xor_sync(0xffffffffu, s, off);
    if ((t & 31) == 0) red[t >> 5] = s;
    __syncthreads();
    if (t == 0) {
        float ss = 0.f;
#pragma unroll
        for (int i = 0; i < 8; i++) ss += red[i];
        s_sum = ss;
    }
    __syncthreads();
    const float inv = 1.0f / s_sum;
    e.x *= inv; e.y *= inv; e.z *= inv; e.w *= inv;
    reinterpret_cast<float4*>(p)[t] = e;
}

// TN: O[t,d] = sum_s attn[s,t] * V[s,d], then gamma blend with xp.
__global__ void out_kernel(const float* __restrict__ gamma, float* __restrict__ out)
{
    __shared__ float As[16][132];
    __shared__ float Bs[16][68];
    const int tid = threadIdx.x;
    const int tx = tid & 15, ty = tid >> 4;
    const int bm0 = blockIdx.y * 128, bn0 = blockIdx.x * 64;
    const int hb = blockIdx.z;
    const int h = hb >> 1, b = hb & 1;
    const float* Aa = g_E + (size_t)hb * SS * SS;   // [s][t]
    const float* Bv = g_V + (size_t)hb * SS * DD;   // [s][d]

    float acc[8][4];
#pragma unroll
    for (int i = 0; i < 8; i++)
#pragma unroll
        for (int j = 0; j < 4; j++) acc[i][j] = 0.f;

    for (int k0 = 0; k0 < SS; k0 += 16) {
#pragma unroll
        for (int p = 0; p < 2; p++) {
            int kk = (tid >> 5) + p * 8;
            int m4 = (tid & 31) * 4;
            float4 v = *reinterpret_cast<const float4*>(Aa + (size_t)(k0 + kk) * SS + bm0 + m4);
            *reinterpret_cast<float4*>(&As[kk][m4]) = v;
        }
        {
            int kk = tid >> 4, n4 = (tid & 15) * 4;
            *reinterpret_cast<float4*>(&Bs[kk][n4]) =
                *reinterpret_cast<const float4*>(Bv + (size_t)(k0 + kk) * DD + bn0 + n4);
        }
        __syncthreads();
#pragma unroll
        for (int kk = 0; kk < 16; kk++) {
            float4 b4 = *reinterpret_cast<const float4*>(&Bs[kk][tx * 4]);
            float4 a0 = *reinterpret_cast<const float4*>(&As[kk][ty * 8]);
            float4 a1 = *reinterpret_cast<const float4*>(&As[kk][ty * 8 + 4]);
            float a[8] = {a0.x, a0.y, a0.z, a0.w, a1.x, a1.y, a1.z, a1.w};
            float b[4] = {b4.x, b4.y, b4.z, b4.w};
#pragma unroll
            for (int i = 0; i < 8; i++)
#pragma unroll
                for (int j = 0; j < 4; j++)
                    acc[i][j] += a[i] * b[j];
        }
        __syncthreads();
    }
    const float g = gamma[h];
    const float inv = 1.0f / (g + 1.0f);
#pragma unroll
    for (int i = 0; i < 8; i++) {
        int t = bm0 + ty * 8 + i;
#pragma unroll
        for (int j = 0; j < 4; j++) {
            int d = bn0 + tx * 4 + j;
            float res = (g * acc[i][j] + g_XP[((size_t)b * SS + t) * DD + d]) * inv;
            out[(((size_t)b * HH + h) * SS + t) * DD + d] = res;
        }
    }
}

extern "C" void kernel_launch(void* const* d_in, const int* in_sizes, int n_in,
                              void* d_out, int out_size)
{
    const float* x     = (const float*)d_in[0];
    const float* y     = (const float*)d_in[1];
    const float* Wq    = (const float*)d_in[2];
    const float* bq    = (const float*)d_in[3];
    const float* Wk    = (const float*)d_in[4];
    const float* bk    = (const float*)d_in[5];
    const float* Wv    = (const float*)d_in[6];
    const float* bv    = (const float*)d_in[7];
    const float* Wp    = (const float*)d_in[8];
    const float* gamma = (const float*)d_in[9];
    const unsigned char* mask_raw = (const unsigned char*)d_in[10];
    float* out = (float*)d_out;

    float *Qp, *Kp, *Vp, *XPp;
    cudaGetSymbolAddress((void**)&Qp,  g_Q);
    cudaGetSymbolAddress((void**)&Kp,  g_K);
    cudaGetSymbolAddress((void**)&Vp,  g_V);
    cudaGetSymbolAddress((void**)&XPp, g_XP);

    normalize_mask_kernel<<<1, 256>>>(mask_raw, SS);

    // Projections: M=2048, N=4096, K=512 (head-major outputs)
    gemm_nn_kernel<<<dim3(64, 16), 256>>>(x, Wq, bq, Qp, 2048, 4096, 512, 1);
    gemm_nn_kernel<<<dim3(64, 16), 256>>>(y, Wk, bk, Kp, 2048, 4096, 512, 1);
    gemm_nn_kernel<<<dim3(64, 16), 256>>>(y, Wv, bv, Vp, 2048, 4096, 512, 1);
    // xp = x @ Wp: M=2048, N=512, K=512
    gemm_nn_kernel<<<dim3(8, 16), 256>>>(x, Wp, nullptr, XPp, 2048, 512, 512, 0);

    // energy + mask: per (h,b): 1024x1024x512
    energy_kernel<<<dim3(16, 8, 16), 256>>>();
    // softmax over rows
    softmax_kernel<<<HH * BB * SS, 256>>>();
    // attn^T @ V + gamma blend
    out_kernel<<<dim3(8, 8, 16), 256>>>(gamma, out);
}

// round 4
// speedup vs baseline: 1.8422x; 1.8404x over previous
#include <cuda_runtime.h>
#include <cuda_bf16.h>
#include <cstdint>

#define BB 2
#define SS 1024
#define DD 512
#define HH 8
#define NEG_INF -1e30f
typedef __nv_bfloat16 bf16;

// ---------------- scratch (device globals) ----------------
__device__ __align__(256) bf16  g_x3[2048*1536];            // [m][ xh | xl | xh ]
__device__ __align__(256) bf16  g_y3[2048*1536];
__device__ __align__(256) bf16  g_W3q[1536*4096];           // rows [Wh ; Wh ; Wl]
__device__ __align__(256) bf16  g_W3k[1536*4096];
__device__ __align__(256) bf16  g_W3v[1536*4096];
__device__ __align__(256) bf16  g_W3p[1536*512];
__device__ __align__(256) bf16  g_Q3 [16*1024*1536];        // [hb][s][ Qh | Ql | Qh ]
__device__ __align__(256) bf16  g_K3T[16*1536*1024];        // [hb][ Kh ; Kh ; Kl ][t]
__device__ __align__(256) bf16  g_V3 [16*3072*512];         // [hb][ Vh ; Vh ; Vl ][d]
__device__ __align__(256) float g_E  [16*1024*1024];        // [hb][s][t]
__device__ __align__(256) bf16  g_E3T[(size_t)16*1024*3072];// [hb][t][ Eh | El | Eh ]
__device__ __align__(256) float g_XP [2048*512];
__device__ int g_mask[SS];

// ---------------- helpers ----------------
__device__ __forceinline__ uint32_t smem_u32(const void* p) {
    uint32_t a;
    asm("{ .reg .u64 t; cvta.to.shared.u64 t, %1; cvt.u32.u64 %0, t; }" : "=r"(a) : "l"(p));
    return a;
}
#define SWZA(x) ((x) ^ (((x) >> 3) & 0x70))   // 128B rows
#define SWZB(x) ((x) ^ (((x) >> 4) & 0x70))   // 256B rows
__device__ __forceinline__ void cp16(uint32_t dst, const void* src) {
    asm volatile("cp.async.cg.shared.global [%0], [%1], 16;" :: "r"(dst), "l"(src));
}
#define CP_COMMIT() asm volatile("cp.async.commit_group;" ::: "memory")
#define CP_WAIT2()  asm volatile("cp.async.wait_group 2;" ::: "memory")
__device__ __forceinline__ void ldm4(uint32_t* d, uint32_t a) {
    asm volatile("ldmatrix.sync.aligned.m8n8.x4.shared.b16 {%0,%1,%2,%3}, [%4];"
                 : "=r"(d[0]), "=r"(d[1]), "=r"(d[2]), "=r"(d[3]) : "r"(a));
}
__device__ __forceinline__ void ldm4t(uint32_t* d, uint32_t a) {
    asm volatile("ldmatrix.sync.aligned.m8n8.x4.trans.shared.b16 {%0,%1,%2,%3}, [%4];"
                 : "=r"(d[0]), "=r"(d[1]), "=r"(d[2]), "=r"(d[3]) : "r"(a));
}
__device__ __forceinline__ void mma16816(float* c, const uint32_t* a, uint32_t b0, uint32_t b1) {
    asm volatile("mma.sync.aligned.m16n8k16.row.col.f32.bf16.bf16.f32 "
                 "{%0,%1,%2,%3}, {%4,%5,%6,%7}, {%8,%9}, {%0,%1,%2,%3};"
                 : "+f"(c[0]), "+f"(c[1]), "+f"(c[2]), "+f"(c[3])
                 : "r"(a[0]), "r"(a[1]), "r"(a[2]), "r"(a[3]), "r"(b0), "r"(b1));
}
__device__ __forceinline__ void split2(float v, bf16& h, bf16& l) {
    h = __float2bfloat16(v);
    l = __float2bfloat16(v - __bfloat162float(h));
}

// ---------------- GEMM: C[M,N] = A[m][k3] * B[k3][n], bf16 mma.sync ----------------
#define SMTOT 131072

__device__ __forceinline__ void load_stage(uint32_t sb, int st, const bf16* A, const bf16* B,
                                           int K3, int ldb, int m0, int n0, int k0, int tid) {
    uint32_t sa = sb + st * 32768, sbb = sa + 16384;
    const char* Ab = (const char*)(A + (size_t)m0 * K3 + k0);
    const char* Bb = (const char*)(B + (size_t)k0 * ldb + n0);
#pragma unroll
    for (int i = 0; i < 4; i++) {
        int idx = tid + i * 256, r = idx >> 3, c = idx & 7;
        cp16(sa + SWZA(r * 128 + c * 16), Ab + (size_t)r * K3 * 2 + c * 16);
    }
#pragma unroll
    for (int i = 0; i < 4; i++) {
        int idx = tid + i * 256, kr = idx >> 4, c = idx & 15;
        cp16(sbb + SWZB(kr * 256 + c * 16), Bb + (size_t)kr * ldb * 2 + c * 16);
    }
}

// EPI: 0=Q proj, 1=K proj(transposed store), 2=V proj, 3=xp, 4=energy+mask, 5=out blend
template<int EPI>
__global__ void __launch_bounds__(256, 1)
gemm_mma(const bf16* __restrict__ A, const bf16* __restrict__ B, int K3, int ldb,
         size_t Az, size_t Bz, const float* __restrict__ bias, float* __restrict__ Cf,
         const float* __restrict__ gamma, const float* __restrict__ XP)
{
    extern __shared__ char smem[];
    const uint32_t sb = smem_u32(smem);
    const int tid = threadIdx.x, wid = tid >> 5, lane = tid & 31;
    const int wm = (wid & 1) * 64, wn = (wid >> 1) * 32;
    const int m0 = blockIdx.y * 128, n0 = blockIdx.x * 128, z = blockIdx.z;
    A += (size_t)z * Az; B += (size_t)z * Bz;

    float c[4][4][4];
#pragma unroll
    for (int i = 0; i < 4; i++)
#pragma unroll
        for (int j = 0; j < 4; j++) { c[i][j][0]=0.f; c[i][j][1]=0.f; c[i][j][2]=0.f; c[i][j][3]=0.f; }

    const int KT = K3 / 64;
#pragma unroll
    for (int s = 0; s < 3; s++) { load_stage(sb, s, A, B, K3, ldb, m0, n0, s * 64, tid); CP_COMMIT(); }

    const int lo16 = lane & 15, hi2 = lane >> 4;
    uint32_t abase[4], bbase[2];
#pragma unroll
    for (int im = 0; im < 4; im++) abase[im] = (wm + im * 16 + lo16) * 128 + hi2 * 16;
#pragma unroll
    for (int in2 = 0; in2 < 2; in2++) bbase[in2] = lo16 * 256 + (wn + in2 * 16 + hi2 * 8) * 2;

    for (int kt = 0; kt < KT; kt++) {
        CP_WAIT2();
        __syncthreads();
        int ls = kt + 3;
        if (ls < KT) load_stage(sb, ls & 3, A, B, K3, ldb, m0, n0, ls * 64, tid);
        CP_COMMIT();
        const uint32_t sa = sb + (kt & 3) * 32768, sbb = sa + 16384;
#pragma unroll
        for (int kk = 0; kk < 4; kk++) {
            uint32_t af[4][4], bf[2][4];
#pragma unroll
            for (int im = 0; im < 4; im++) ldm4(af[im], sa + SWZA(abase[im] + kk * 32));
#pragma unroll
            for (int in2 = 0; in2 < 2; in2++) ldm4t(bf[in2], sbb + SWZB(bbase[in2] + kk * 4096));
#pragma unroll
            for (int im = 0; im < 4; im++)
#pragma unroll
                for (int in2 = 0; in2 < 2; in2++) {
                    mma16816(c[im][in2 * 2],     af[im], bf[in2][0], bf[in2][1]);
                    mma16816(c[im][in2 * 2 + 1], af[im], bf[in2][2], bf[in2][3]);
                }
        }
    }
    __syncthreads();

    // stage accumulators to smem
    float* stf = (float*)smem;
    const int rin = lane >> 2, cp2 = (lane & 3) * 2;
#pragma unroll
    for (int im = 0; im < 4; im++)
#pragma unroll
        for (int i8 = 0; i8 < 4; i8++) {
            int rr = wm + im * 16 + rin, cc = wn + i8 * 8 + cp2;
            stf[rr * 129 + cc]       = c[im][i8][0];
            stf[rr * 129 + cc + 1]   = c[im][i8][1];
            stf[(rr + 8) * 129 + cc]     = c[im][i8][2];
            stf[(rr + 8) * 129 + cc + 1] = c[im][i8][3];
        }
    __syncthreads();

#pragma unroll 4
    for (int i = 0; i < 64; i++) {
        const int idx = tid + i * 256;
        int r, cc;
        if (EPI == 1) { r = idx & 127; cc = idx >> 7; } else { r = idx >> 7; cc = idx & 127; }
        float v = stf[r * 129 + cc];
        const int row2 = m0 + r, col = n0 + cc;
        if (EPI == 0) {
            v += __ldg(bias + col);
            int h = col >> 9, d = col & 511;
            bf16 hi, lo; split2(v, hi, lo);
            size_t base = ((size_t)h * 2048 + row2) * 1536 + d;
            g_Q3[base] = hi; g_Q3[base + 512] = lo; g_Q3[base + 1024] = hi;
        } else if (EPI == 1) {
            v += __ldg(bias + col);
            int h = col >> 9, d = col & 511;
            int b = row2 >> 10, t = row2 & 1023;
            bf16 hi, lo; split2(v, hi, lo);
            size_t base = (size_t)(h * 2 + b) * 1536 * 1024 + (size_t)d * 1024 + t;
            g_K3T[base] = hi; g_K3T[base + 512 * 1024] = hi; g_K3T[base + 1024 * 1024] = lo;
        } else if (EPI == 2) {
            v += __ldg(bias + col);
            int h = col >> 9, d = col & 511;
            int b = row2 >> 10, s = row2 & 1023;
            bf16 hi, lo; split2(v, hi, lo);
            size_t base = (size_t)(h * 2 + b) * 3072 * 512 + (size_t)s * 512 + d;
            g_V3[base] = hi; g_V3[base + 1024 * 512] = hi; g_V3[base + 2048 * 512] = lo;
        } else if (EPI == 3) {
            Cf[(size_t)row2 * 512 + col] = v;
        } else if (EPI == 4) {
            g_E[(size_t)z * 1048576 + (size_t)row2 * 1024 + col] = g_mask[col] ? v : NEG_INF;
        } else {
            const int h = z >> 1, b = z & 1;
            float g = __ldg(gamma + h);
            float xp = __ldg(XP + ((size_t)b * 1024 + row2) * 512 + col);
            Cf[(((size_t)(b * 8 + h)) * 1024 + row2) * 512 + col] = (g * v + xp) * (1.0f / (g + 1.0f));
        }
    }
}

// ---------------- aux ----------------
__global__ void normalize_mask_kernel(const unsigned char* __restrict__ raw, int n) {
    __shared__ int s_c0, s_chi;
    if (threadIdx.x == 0) { s_c0 = 0; s_chi = 0; }
    __syncthreads();
    int c0 = 0, chi = 0;
    for (int t = threadIdx.x; t < 256; t += blockDim.x) {
        unsigned char b0 = raw[4*t], b1 = raw[4*t+1], b2 = raw[4*t+2], b3 = raw[4*t+3];
        if (b0) c0++;
        if (b1 | b2 | b3) chi++;
    }
    atomicAdd(&s_c0, c0); atomicAdd(&s_chi, chi);
    __syncthreads();
    int mode = (s_chi == 0) ? 1 : (s_c0 == 0 ? 2 : 0);
    for (int t = threadIdx.x; t < n; t += blockDim.x) {
        int v;
        if (mode == 0) v = (raw[t] != 0);
        else if (mode == 1) v = (((const int*)raw)[t] != 0);
        else v = (((const float*)raw)[t] != 0.0f);
        g_mask[t] = v;
    }
}

// x -> [xh | xl | xh] along k (rows m of length 1536)
__global__ void splitX(const float* __restrict__ in, bf16* __restrict__ out) {
    int i = blockIdx.x * 256 + threadIdx.x;          // i < 2048*512
    int m = i >> 9, k = i & 511;
    bf16 h, l; split2(in[i], h, l);
    size_t base = (size_t)m * 1536 + k;
    out[base] = h; out[base + 512] = l; out[base + 1024] = h;
}

// W [512][N] -> rows [Wh ; Wh ; Wl]  (n = 512*N)
__global__ void splitW(const float* __restrict__ in, bf16* __restrict__ out, int n) {
    int i = blockIdx.x * 256 + threadIdx.x;
    if (i < n) {
        bf16 h, l; split2(in[i], h, l);
        out[i] = h; out[n + i] = h; out[2 * n + i] = l;
    }
}

__global__ void softmax_kernel(void) {
    const size_t row = blockIdx.x;
    float* p = g_E + row * SS;
    const int t = threadIdx.x;
    float4 v = reinterpret_cast<float4*>(p)[t];
    float mx = fmaxf(fmaxf(v.x, v.y), fmaxf(v.z, v.w));
    __shared__ float red[8]; __shared__ float s_max, s_sum;
#pragma unroll
    for (int o = 16; o > 0; o >>= 1) mx = fmaxf(mx, __shfl_xor_sync(~0u, mx, o));
    if ((t & 31) == 0) red[t >> 5] = mx;
    __syncthreads();
    if (t == 0) { float m = red[0]; for (int i = 1; i < 8; i++) m = fmaxf(m, red[i]); s_max = m; }
    __syncthreads();
    const float m = s_max;
    float4 e = {__expf(v.x-m), __expf(v.y-m), __expf(v.z-m), __expf(v.w-m)};
    float s = e.x + e.y + e.z + e.w;
#pragma unroll
    for (int o = 16; o > 0; o >>= 1) s += __shfl_xor_sync(~0u, s, o);
    if ((t & 31) == 0) red[t >> 5] = s;
    __syncthreads();
    if (t == 0) { float ss = 0.f; for (int i = 0; i < 8; i++) ss += red[i]; s_sum = ss; }
    __syncthreads();
    const float inv = 1.0f / s_sum;
    e.x *= inv; e.y *= inv; e.z *= inv; e.w *= inv;
    reinterpret_cast<float4*>(p)[t] = e;
}

// E [z][s][t] f32 -> E3T [z][t][ Eh | El | Eh ] (cols s, s+1024:lo? no: +0 hi, +1024 lo, +2048 hi)
__global__ void transE(void) {
    __shared__ float tile[32][33];
    const int z = blockIdx.z;
    const float* in = g_E + (size_t)z * 1048576;
    bf16* out = g_E3T + (size_t)z * 1024 * 3072;
    const int c0 = blockIdx.x * 32, r0 = blockIdx.y * 32;   // c0: t, r0: s
    const int tx = threadIdx.x, ty = threadIdx.y;
#pragma unroll
    for (int i = 0; i < 4; i++)
        tile[ty + i * 8][tx] = in[(size_t)(r0 + ty + i * 8) * 1024 + c0 + tx];
    __syncthreads();
#pragma unroll
    for (int i = 0; i < 4; i++) {
        float v = tile[tx][ty + i * 8];
        bf16 h, l; split2(v, h, l);
        size_t base = (size_t)(c0 + ty + i * 8) * 3072 + r0 + tx;
        out[base] = h; out[base + 1024] = l; out[base + 2048] = h;
    }
}

// ---------------- launch ----------------
template<int EPI>
static void launch_gemm(dim3 grid, const bf16* A, const bf16* B, int K3, int ldb,
                        size_t Az, size_t Bz, const float* bias, float* Cf,
                        const float* gamma, const float* XP) {
    static bool done = false;
    if (!done) { cudaFuncSetAttribute(gemm_mma<EPI>, cudaFuncAttributeMaxDynamicSharedMemorySize, SMTOT); done = true; }
    gemm_mma<EPI><<<grid, 256, SMTOT>>>(A, B, K3, ldb, Az, Bz, bias, Cf, gamma, XP);
}

extern "C" void kernel_launch(void* const* d_in, const int* in_sizes, int n_in,
                              void* d_out, int out_size)
{
    const float* x = (const float*)d_in[0];
    const float* y = (const float*)d_in[1];
    const float* Wq = (const float*)d_in[2];
    const float* bq = (const float*)d_in[3];
    const float* Wk = (const float*)d_in[4];
    const float* bk = (const float*)d_in[5];
    const float* Wv = (const float*)d_in[6];
    const float* bv = (const float*)d_in[7];
    const float* Wp = (const float*)d_in[8];
    const float* gamma = (const float*)d_in[9];
    const unsigned char* mask_raw = (const unsigned char*)d_in[10];
    float* out = (float*)d_out;

    bf16 *x3, *y3, *W3q, *W3k, *W3v, *W3p, *Q3, *K3T, *V3, *E3T;
    float *XP;
    cudaGetSymbolAddress((void**)&x3, g_x3);   cudaGetSymbolAddress((void**)&y3, g_y3);
    cudaGetSymbolAddress((void**)&W3q, g_W3q); cudaGetSymbolAddress((void**)&W3k, g_W3k);
    cudaGetSymbolAddress((void**)&W3v, g_W3v); cudaGetSymbolAddress((void**)&W3p, g_W3p);
    cudaGetSymbolAddress((void**)&Q3, g_Q3);   cudaGetSymbolAddress((void**)&K3T, g_K3T);
    cudaGetSymbolAddress((void**)&V3, g_V3);   cudaGetSymbolAddress((void**)&E3T, g_E3T);
    cudaGetSymbolAddress((void**)&XP, g_XP);

    normalize_mask_kernel<<<1, 256>>>(mask_raw, SS);
    splitX<<<4096, 256>>>(x, x3);
    splitX<<<4096, 256>>>(y, y3);
    splitW<<<8192, 256>>>(Wq, W3q, 512 * 4096);
    splitW<<<8192, 256>>>(Wk, W3k, 512 * 4096);
    splitW<<<8192, 256>>>(Wv, W3v, 512 * 4096);
    splitW<<<1024, 256>>>(Wp, W3p, 512 * 512);

    // projections: M=2048, N=4096, K3=1536
    launch_gemm<0>(dim3(32, 16, 1), x3, W3q, 1536, 4096, 0, 0, bq, nullptr, nullptr, nullptr);
    launch_gemm<1>(dim3(32, 16, 1), y3, W3k, 1536, 4096, 0, 0, bk, nullptr, nullptr, nullptr);
    launch_gemm<2>(dim3(32, 16, 1), y3, W3v, 1536, 4096, 0, 0, bv, nullptr, nullptr, nullptr);
    // xp: M=2048, N=512, K3=1536
    launch_gemm<3>(dim3(4, 16, 1), x3, W3p, 1536, 512, 0, 0, nullptr, XP, nullptr, nullptr);
    // energy per hb: M=N=1024, K3=1536
    launch_gemm<4>(dim3(8, 8, 16), Q3, K3T, 1536, 1024,
                   (size_t)1024 * 1536, (size_t)1536 * 1024, nullptr, nullptr, nullptr, nullptr);
    softmax_kernel<<<16384, 256>>>();
    transE<<<dim3(32, 32, 16), dim3(32, 8)>>>();
    // out per hb: M=1024 (t), N=512 (d), K3=3072
    launch_gemm<5>(dim3(4, 8, 16), E3T, V3, 3072, 512,
                   (size_t)1024 * 3072, (size_t)3072 * 512, nullptr, out, gamma, XP);
}

// round 5
// speedup vs baseline: 2.4237x; 1.3157x over previous
#include <cuda_runtime.h>
#include <cuda_fp16.h>
#include <cstdint>

#define SSZ 1024
#define NEG_INF -1e30f
typedef __half fp16;

// ---------------- scratch ----------------
__device__ __align__(256) fp16  g_x3[2048*1536];             // [m][ xh | xl | xh ]
__device__ __align__(256) fp16  g_y3[2048*1536];
__device__ __align__(256) fp16  g_W3q[1536*4096];            // [ Wh ; Wh ; Wl ]
__device__ __align__(256) fp16  g_W3k[1536*4096];
__device__ __align__(256) fp16  g_W3v[1536*4096];
__device__ __align__(256) fp16  g_W3p[1536*512];
__device__ __align__(256) fp16  g_Q3 [16*1024*1536];         // [hb][s][ Qh | Ql | Qh ]
__device__ __align__(256) fp16  g_K3T[16*1536*1024];         // [hb][ Kh ; Kh ; Kl ][t]
__device__ __align__(256) fp16  g_V1 [16*1024*512];          // [hb][s][d] fp16 (1-pass)
__device__ __align__(256) float g_E  [(size_t)16*1024*1024]; // [hb][s][t]
__device__ __align__(256) fp16  g_ET [(size_t)16*1024*1024]; // [hb][t][s] fp16
__device__ __align__(256) float g_XP [2048*512];
__device__ int g_mask[SSZ];

// ---------------- helpers ----------------
__device__ __forceinline__ uint32_t smem_u32(const void* p) {
    uint32_t a;
    asm("{ .reg .u64 t; cvta.to.shared.u64 t, %1; cvt.u32.u64 %0, t; }" : "=r"(a) : "l"(p));
    return a;
}
#define SWZA(x) ((x) ^ (((x) >> 3) & 0x70))   // 128B rows
#define SWZB(x) ((x) ^ (((x) >> 4) & 0x70))   // 256B rows
__device__ __forceinline__ void cp16(uint32_t dst, const void* src) {
    asm volatile("cp.async.cg.shared.global [%0], [%1], 16;" :: "r"(dst), "l"(src));
}
#define CP_COMMIT() asm volatile("cp.async.commit_group;" ::: "memory")
#define CP_WAIT1()  asm volatile("cp.async.wait_group 1;" ::: "memory")
__device__ __forceinline__ void ldm4(uint32_t* d, uint32_t a) {
    asm volatile("ldmatrix.sync.aligned.m8n8.x4.shared.b16 {%0,%1,%2,%3}, [%4];"
                 : "=r"(d[0]), "=r"(d[1]), "=r"(d[2]), "=r"(d[3]) : "r"(a));
}
__device__ __forceinline__ void ldm4t(uint32_t* d, uint32_t a) {
    asm volatile("ldmatrix.sync.aligned.m8n8.x4.trans.shared.b16 {%0,%1,%2,%3}, [%4];"
                 : "=r"(d[0]), "=r"(d[1]), "=r"(d[2]), "=r"(d[3]) : "r"(a));
}
__device__ __forceinline__ void mma16816(float* c, const uint32_t* a, uint32_t b0, uint32_t b1) {
    asm volatile("mma.sync.aligned.m16n8k16.row.col.f32.f16.f16.f32 "
                 "{%0,%1,%2,%3}, {%4,%5,%6,%7}, {%8,%9}, {%0,%1,%2,%3};"
                 : "+f"(c[0]), "+f"(c[1]), "+f"(c[2]), "+f"(c[3])
                 : "r"(a[0]), "r"(a[1]), "r"(a[2]), "r"(a[3]), "r"(b0), "r"(b1));
}
__device__ __forceinline__ void split2(float v, fp16& h, fp16& l) {
    h = __float2half(v);
    l = __float2half(v - __half2float(h));
}

// ---------------- GEMM: CTA 256x128, warp 64x64, K-stage 64, 3 stages ----------------
#define STG 49152
#define SMTOT (3*STG)

__device__ __forceinline__ void load_stage(uint32_t sb, int st, const fp16* A, int lda,
                                           const fp16* B, int ldb, int m0, int n0, int k0, int tid) {
    uint32_t sa = sb + st * STG, sbb = sa + 32768;
    const fp16* Ab = A + (size_t)m0 * lda + k0;
    const fp16* Bb = B + (size_t)k0 * ldb + n0;
#pragma unroll
    for (int i = 0; i < 8; i++) {
        int idx = tid + i * 256, r = idx >> 3, c = idx & 7;
        cp16(sa + SWZA(r * 128 + c * 16), Ab + (size_t)r * lda + c * 8);
    }
#pragma unroll
    for (int i = 0; i < 4; i++) {
        int idx = tid + i * 256, kr = idx >> 4, c = idx & 15;
        cp16(sbb + SWZB(kr * 256 + c * 16), Bb + (size_t)kr * ldb + c * 8);
    }
}

// EPI: 0=Q proj, 1=K proj(transposed), 2=V proj fp16, 3=xp f32, 4=energy+mask, 5=out blend
template<int EPI>
__global__ void __launch_bounds__(256, 1)
gemm_mma(const fp16* __restrict__ A, int lda, const fp16* __restrict__ B, int ldb, int K,
         size_t Az, size_t Bz, const float* __restrict__ bias, float* __restrict__ Cf,
         const float* __restrict__ gamma, const float* __restrict__ XP)
{
    extern __shared__ char smem[];
    const uint32_t sb = smem_u32(smem);
    const int tid = threadIdx.x, wid = tid >> 5, lane = tid & 31;
    const int wm = (wid & 3) * 64, wn = (wid >> 2) * 64;
    const int m0 = blockIdx.y * 256, n0 = blockIdx.x * 128, z = blockIdx.z;
    A += (size_t)z * Az; B += (size_t)z * Bz;

    float c[4][8][4];
#pragma unroll
    for (int i = 0; i < 4; i++)
#pragma unroll
        for (int j = 0; j < 8; j++)
#pragma unroll
            for (int q = 0; q < 4; q++) c[i][j][q] = 0.f;

    const int KT = K / 64;
    load_stage(sb, 0, A, lda, B, ldb, m0, n0, 0, tid); CP_COMMIT();
    load_stage(sb, 1, A, lda, B, ldb, m0, n0, 64, tid); CP_COMMIT();

    const int lo16 = lane & 15, hi2 = lane >> 4;
    uint32_t abase[4], bbase[4];
#pragma unroll
    for (int im = 0; im < 4; im++) abase[im] = (wm + im * 16 + lo16) * 128 + hi2 * 16;
#pragma unroll
    for (int in2 = 0; in2 < 4; in2++) bbase[in2] = lo16 * 256 + (wn + in2 * 16 + hi2 * 8) * 2;

    int st = 0;
    for (int kt = 0; kt < KT; kt++) {
        CP_WAIT1();
        __syncthreads();
        int ls = kt + 2;
        if (ls < KT) {
            int st2 = st + 2; if (st2 >= 3) st2 -= 3;
            load_stage(sb, st2, A, lda, B, ldb, m0, n0, ls * 64, tid);
        }
        CP_COMMIT();
        const uint32_t sa = sb + st * STG, sbb = sa + 32768;
#pragma unroll
        for (int kk = 0; kk < 4; kk++) {
            uint32_t af[4][4], bf[4][4];
#pragma unroll
            for (int im = 0; im < 4; im++) ldm4(af[im], sa + SWZA(abase[im] + kk * 32));
#pragma unroll
            for (int in2 = 0; in2 < 4; in2++) ldm4t(bf[in2], sbb + SWZB(bbase[in2] + kk * 4096));
#pragma unroll
            for (int im = 0; im < 4; im++)
#pragma unroll
                for (int in2 = 0; in2 < 4; in2++) {
                    mma16816(c[im][in2 * 2],     af[im], bf[in2][0], bf[in2][1]);
                    mma16816(c[im][in2 * 2 + 1], af[im], bf[in2][2], bf[in2][3]);
                }
        }
        if (++st == 3) st = 0;
        __syncthreads();
    }

    // stage accumulators -> smem (256 x 129 floats)
    float* stf = (float*)smem;
    const int rin = lane >> 2, cp2 = (lane & 3) * 2;
#pragma unroll
    for (int im = 0; im < 4; im++)
#pragma unroll
        for (int i8 = 0; i8 < 8; i8++) {
            int rr = wm + im * 16 + rin, cc = wn + i8 * 8 + cp2;
            stf[rr * 129 + cc]           = c[im][i8][0];
            stf[rr * 129 + cc + 1]       = c[im][i8][1];
            stf[(rr + 8) * 129 + cc]     = c[im][i8][2];
            stf[(rr + 8) * 129 + cc + 1] = c[im][i8][3];
        }
    __syncthreads();

#pragma unroll 4
    for (int i = 0; i < 128; i++) {
        const int idx = tid + i * 256;
        int r, cc;
        if (EPI == 1) { r = idx & 255; cc = idx >> 8; } else { r = idx >> 7; cc = idx & 127; }
        float v = stf[r * 129 + cc];
        const int row2 = m0 + r, col = n0 + cc;
        if (EPI == 0) {
            v += __ldg(bias + col);
            int h = col >> 9, d = col & 511;
            fp16 hi, lo; split2(v, hi, lo);
            size_t base = ((size_t)h * 2048 + row2) * 1536 + d;
            g_Q3[base] = hi; g_Q3[base + 512] = lo; g_Q3[base + 1024] = hi;
        } else if (EPI == 1) {
            v += __ldg(bias + col);
            int h = col >> 9, d = col & 511;
            int b = row2 >> 10, t = row2 & 1023;
            fp16 hi, lo; split2(v, hi, lo);
            size_t base = (size_t)(h * 2 + b) * 1536 * 1024 + (size_t)d * 1024 + t;
            g_K3T[base] = hi; g_K3T[base + 512 * 1024] = hi; g_K3T[base + 1024 * 1024] = lo;
        } else if (EPI == 2) {
            v += __ldg(bias + col);
            int h = col >> 9, d = col & 511;
            int b = row2 >> 10, s = row2 & 1023;
            g_V1[(size_t)(h * 2 + b) * 1024 * 512 + (size_t)s * 512 + d] = __float2half(v);
        } else if (EPI == 3) {
            Cf[(size_t)row2 * 512 + col] = v;
        } else if (EPI == 4) {
            g_E[(size_t)z * 1048576 + (size_t)row2 * 1024 + col] = g_mask[col] ? v : NEG_INF;
        } else {
            const int h = z >> 1, b = z & 1;
            float g = __ldg(gamma + h);
            float xp = __ldg(XP + ((size_t)b * 1024 + row2) * 512 + col);
            Cf[(((size_t)(b * 8 + h)) * 1024 + row2) * 512 + col] = (g * v + xp) * (1.0f / (g + 1.0f));
        }
    }
}

// ---------------- aux ----------------
__global__ void normalize_mask_kernel(const unsigned char* __restrict__ raw, int n) {
    __shared__ int s_c0, s_chi;
    if (threadIdx.x == 0) { s_c0 = 0; s_chi = 0; }
    __syncthreads();
    int c0 = 0, chi = 0;
    for (int t = threadIdx.x; t < 256; t += blockDim.x) {
        unsigned char b0 = raw[4*t], b1 = raw[4*t+1], b2 = raw[4*t+2], b3 = raw[4*t+3];
        if (b0) c0++;
        if (b1 | b2 | b3) chi++;
    }
    atomicAdd(&s_c0, c0); atomicAdd(&s_chi, chi);
    __syncthreads();
    int mode = (s_chi == 0) ? 1 : (s_c0 == 0 ? 2 : 0);
    for (int t = threadIdx.x; t < n; t += blockDim.x) {
        int v;
        if (mode == 0) v = (raw[t] != 0);
        else if (mode == 1) v = (((const int*)raw)[t] != 0);
        else v = (((const float*)raw)[t] != 0.0f);
        g_mask[t] = v;
    }
}

__global__ void splitX(const float* __restrict__ in, fp16* __restrict__ out) {
    int i = blockIdx.x * 256 + threadIdx.x;
    int m = i >> 9, k = i & 511;
    fp16 h, l; split2(in[i], h, l);
    size_t base = (size_t)m * 1536 + k;
    out[base] = h; out[base + 512] = l; out[base + 1024] = h;
}

__global__ void splitW(const float* __restrict__ in, fp16* __restrict__ out, int n) {
    int i = blockIdx.x * 256 + threadIdx.x;
    if (i < n) {
        fp16 h, l; split2(in[i], h, l);
        out[i] = h; out[n + i] = h; out[2 * n + i] = l;
    }
}

__global__ void softmax_kernel(void) {
    const size_t row = blockIdx.x;
    float* p = g_E + row * SSZ;
    const int t = threadIdx.x;
    float4 v = reinterpret_cast<float4*>(p)[t];
    float mx = fmaxf(fmaxf(v.x, v.y), fmaxf(v.z, v.w));
    __shared__ float red[8]; __shared__ float s_max, s_sum;
#pragma unroll
    for (int o = 16; o > 0; o >>= 1) mx = fmaxf(mx, __shfl_xor_sync(~0u, mx, o));
    if ((t & 31) == 0) red[t >> 5] = mx;
    __syncthreads();
    if (t == 0) { float m = red[0]; for (int i = 1; i < 8; i++) m = fmaxf(m, red[i]); s_max = m; }
    __syncthreads();
    const float m = s_max;
    float4 e = {__expf(v.x-m), __expf(v.y-m), __expf(v.z-m), __expf(v.w-m)};
    float s = e.x + e.y + e.z + e.w;
#pragma unroll
    for (int o = 16; o > 0; o >>= 1) s += __shfl_xor_sync(~0u, s, o);
    if ((t & 31) == 0) red[t >> 5] = s;
    __syncthreads();
    if (t == 0) { float ss = 0.f; for (int i = 0; i < 8; i++) ss += red[i]; s_sum = ss; }
    __syncthreads();
    const float inv = 1.0f / s_sum;
    e.x *= inv; e.y *= inv; e.z *= inv; e.w *= inv;
    reinterpret_cast<float4*>(p)[t] = e;
}

// E [z][s][t] f32 -> ET [z][t][s] fp16
__global__ void transE(void) {
    __shared__ float tile[32][33];
    const int z = blockIdx.z;
    const float* in = g_E + (size_t)z * 1048576;
    fp16* out = g_ET + (size_t)z * 1048576;
    const int c0 = blockIdx.x * 32, r0 = blockIdx.y * 32;
    const int tx = threadIdx.x, ty = threadIdx.y;
#pragma unroll
    for (int i = 0; i < 4; i++)
        tile[ty + i * 8][tx] = in[(size_t)(r0 + ty + i * 8) * 1024 + c0 + tx];
    __syncthreads();
#pragma unroll
    for (int i = 0; i < 4; i++)
        out[(size_t)(c0 + ty + i * 8) * 1024 + r0 + tx] = __float2half(tile[tx][ty + i * 8]);
}

// ---------------- launch ----------------
template<int EPI>
static void launch_gemm(dim3 grid, const fp16* A, int lda, const fp16* B, int ldb, int K,
                        size_t Az, size_t Bz, const float* bias, float* Cf,
                        const float* gamma, const float* XP) {
    static bool done = false;
    if (!done) { cudaFuncSetAttribute(gemm_mma<EPI>, cudaFuncAttributeMaxDynamicSharedMemorySize, SMTOT); done = true; }
    gemm_mma<EPI><<<grid, 256, SMTOT>>>(A, lda, B, ldb, K, Az, Bz, bias, Cf, gamma, XP);
}

extern "C" void kernel_launch(void* const* d_in, const int* in_sizes, int n_in,
                              void* d_out, int out_size)
{
    const float* x = (const float*)d_in[0];
    const float* y = (const float*)d_in[1];
    const float* Wq = (const float*)d_in[2];
    const float* bq = (const float*)d_in[3];
    const float* Wk = (const float*)d_in[4];
    const float* bk = (const float*)d_in[5];
    const float* Wv = (const float*)d_in[6];
    const float* bv = (const float*)d_in[7];
    const float* Wp = (const float*)d_in[8];
    const float* gamma = (const float*)d_in[9];
    const unsigned char* mask_raw = (const unsigned char*)d_in[10];
    float* out = (float*)d_out;

    fp16 *x3, *y3, *W3q, *W3k, *W3v, *W3p, *Q3, *K3T, *V1, *ET;
    float *XP;
    cudaGetSymbolAddress((void**)&x3, g_x3);   cudaGetSymbolAddress((void**)&y3, g_y3);
    cudaGetSymbolAddress((void**)&W3q, g_W3q); cudaGetSymbolAddress((void**)&W3k, g_W3k);
    cudaGetSymbolAddress((void**)&W3v, g_W3v); cudaGetSymbolAddress((void**)&W3p, g_W3p);
    cudaGetSymbolAddress((void**)&Q3, g_Q3);   cudaGetSymbolAddress((void**)&K3T, g_K3T);
    cudaGetSymbolAddress((void**)&V1, g_V1);   cudaGetSymbolAddress((void**)&ET, g_ET);
    cudaGetSymbolAddress((void**)&XP, g_XP);

    normalize_mask_kernel<<<1, 256>>>(mask_raw, SSZ);
    splitX<<<4096, 256>>>(x, x3);
    splitX<<<4096, 256>>>(y, y3);
    splitW<<<8192, 256>>>(Wq, W3q, 512 * 4096);
    splitW<<<8192, 256>>>(Wk, W3k, 512 * 4096);
    splitW<<<8192, 256>>>(Wv, W3v, 512 * 4096);
    splitW<<<1024, 256>>>(Wp, W3p, 512 * 512);

    // Q,K projections: M=2048, N=4096, K=1536 (3-pass)
    launch_gemm<0>(dim3(32, 8, 1), x3, 1536, W3q, 4096, 1536, 0, 0, bq, nullptr, nullptr, nullptr);
    launch_gemm<1>(dim3(32, 8, 1), y3, 1536, W3k, 4096, 1536, 0, 0, bk, nullptr, nullptr, nullptr);
    // V projection: 1-pass fp16 (hi blocks only: lda=1536, K=512; W3v rows 0..511 = Wh)
    launch_gemm<2>(dim3(32, 8, 1), y3, 1536, W3v, 4096, 512, 0, 0, bv, nullptr, nullptr, nullptr);
    // xp: M=2048, N=512, K=1536 (3-pass)
    launch_gemm<3>(dim3(4, 8, 1), x3, 1536, W3p, 512, 1536, 0, 0, nullptr, XP, nullptr, nullptr);
    // energy per hb: M=N=1024, K=1536 (3-pass)
    launch_gemm<4>(dim3(8, 4, 16), Q3, 1536, K3T, 1024, 1536,
                   (size_t)1024 * 1536, (size_t)1536 * 1024, nullptr, nullptr, nullptr, nullptr);
    softmax_kernel<<<16384, 256>>>();
    transE<<<dim3(32, 32, 16), dim3(32, 8)>>>();
    // out per hb: M=1024 (t), N=512 (d), K=1024 (1-pass fp16)
    launch_gemm<5>(dim3(4, 4, 16), ET, 1024, V1, 512, 1024,
                   (size_t)1024 * 1024, (size_t)1024 * 512, nullptr, out, gamma, XP);
}

// round 6
// speedup vs baseline: 2.6750x; 1.1037x over previous
#include <cuda_runtime.h>
#include <cuda_fp16.h>
#include <cstdint>

#define SSZ 1024
#define NEG_INF -1e30f
typedef __half fp16;

// ---------------- scratch ----------------
__device__ __align__(256) fp16  g_x3[2048*1536];              // [m][ xh | xl | xh ]
__device__ __align__(256) fp16  g_y3[2048*1536];
__device__ __align__(256) fp16  g_W3qp[1536*4608];            // [Wq3 | Wp3] packed, ld 4608
__device__ __align__(256) fp16  g_W3k[1536*4096];
__device__ __align__(256) fp16  g_Wvh[512*4096];              // hi-only
__device__ __align__(256) fp16  g_Q3 [16*1024*1536];          // [h][2048 rows][ Qh | Ql | Qh ]
__device__ __align__(256) fp16  g_K3T[16*1536*1024];          // [hb][ Kh ; Kh ; Kl ][t]
__device__ __align__(256) fp16  g_V1T[16*512*1024];           // [hb][d][s] fp16
__device__ __align__(256) float g_E  [(size_t)16*1024*1024];  // [hb][s][t] f32
__device__ __align__(256) fp16  g_AF [(size_t)16*1024*1024];  // [hb][s][t] fp16 attn
__device__ __align__(256) float g_XP [2048*512];
__device__ int g_mask[SSZ];

// ---------------- helpers ----------------
__device__ __forceinline__ uint32_t smem_u32(const void* p) {
    uint32_t a;
    asm("{ .reg .u64 t; cvta.to.shared.u64 t, %1; cvt.u32.u64 %0, t; }" : "=r"(a) : "l"(p));
    return a;
}
#define SWZA(x) ((x) ^ (((x) >> 3) & 0x70))   // 128B rows
#define SWZB(x) ((x) ^ (((x) >> 4) & 0x70))   // 256B rows
__device__ __forceinline__ void cp16(uint32_t dst, const void* src) {
    asm volatile("cp.async.cg.shared.global [%0], [%1], 16;" :: "r"(dst), "l"(src));
}
#define CP_COMMIT() asm volatile("cp.async.commit_group;" ::: "memory")
#define CP_WAIT2()  asm volatile("cp.async.wait_group 2;" ::: "memory")
__device__ __forceinline__ void ldm4(uint32_t* d, uint32_t a) {
    asm volatile("ldmatrix.sync.aligned.m8n8.x4.shared.b16 {%0,%1,%2,%3}, [%4];"
                 : "=r"(d[0]), "=r"(d[1]), "=r"(d[2]), "=r"(d[3]) : "r"(a));
}
__device__ __forceinline__ void ldm4t(uint32_t* d, uint32_t a) {
    asm volatile("ldmatrix.sync.aligned.m8n8.x4.trans.shared.b16 {%0,%1,%2,%3}, [%4];"
                 : "=r"(d[0]), "=r"(d[1]), "=r"(d[2]), "=r"(d[3]) : "r"(a));
}
__device__ __forceinline__ void mma16816(float* c, const uint32_t* a, uint32_t b0, uint32_t b1) {
    asm volatile("mma.sync.aligned.m16n8k16.row.col.f32.f16.f16.f32 "
                 "{%0,%1,%2,%3}, {%4,%5,%6,%7}, {%8,%9}, {%0,%1,%2,%3};"
                 : "+f"(c[0]), "+f"(c[1]), "+f"(c[2]), "+f"(c[3])
                 : "r"(a[0]), "r"(a[1]), "r"(a[2]), "r"(a[3]), "r"(b0), "r"(b1));
}
__device__ __forceinline__ void split2(float v, fp16& h, fp16& l) {
    h = __float2half(v);
    l = __float2half(v - __half2float(h));
}

// ---------------- GEMM: CTA 256x128, warp 64x64, K-stage 64, 4 stages ----------------
#define STG 49152
#define SMTOT (4*STG)

__device__ __forceinline__ void load_stage(uint32_t sb, int st, const fp16* A, int lda,
                                           const fp16* B, int ldb, int m0, int n0, int k0, int tid) {
    uint32_t sa = sb + st * STG, sbb = sa + 32768;
    const fp16* Ab = A + (size_t)m0 * lda + k0;
    const fp16* Bb = B + (size_t)k0 * ldb + n0;
#pragma unroll
    for (int i = 0; i < 8; i++) {
        int idx = tid + i * 256, r = idx >> 3, c = idx & 7;
        cp16(sa + SWZA(r * 128 + c * 16), Ab + (size_t)r * lda + c * 8);
    }
#pragma unroll
    for (int i = 0; i < 4; i++) {
        int idx = tid + i * 256, kr = idx >> 4, c = idx & 15;
        cp16(sbb + SWZB(kr * 256 + c * 16), Bb + (size_t)kr * ldb + c * 8);
    }
}

// EPI: 0=Q proj + xp (N=4608), 1=K proj(transposed), 2=V proj(transposed fp16),
//      4=energy+mask, 5=out blend (tile is [d][t])
template<int EPI>
__global__ void __launch_bounds__(256, 1)
gemm_mma(const fp16* __restrict__ A, int lda, const fp16* __restrict__ B, int ldb, int K,
         size_t Az, size_t Bz, const float* __restrict__ bias, float* __restrict__ Cf,
         const float* __restrict__ gamma, const float* __restrict__ XP)
{
    extern __shared__ char smem[];
    const uint32_t sb = smem_u32(smem);
    const int tid = threadIdx.x, wid = tid >> 5, lane = tid & 31;
    const int wm = (wid & 3) * 64, wn = (wid >> 2) * 64;
    const int m0 = blockIdx.y * 256, n0 = blockIdx.x * 128, z = blockIdx.z;
    A += (size_t)z * Az; B += (size_t)z * Bz;

    float c[4][8][4];
#pragma unroll
    for (int i = 0; i < 4; i++)
#pragma unroll
        for (int j = 0; j < 8; j++)
#pragma unroll
            for (int q = 0; q < 4; q++) c[i][j][q] = 0.f;

    const int KT = K / 64;
    load_stage(sb, 0, A, lda, B, ldb, m0, n0, 0, tid); CP_COMMIT();
    load_stage(sb, 1, A, lda, B, ldb, m0, n0, 64, tid); CP_COMMIT();
    load_stage(sb, 2, A, lda, B, ldb, m0, n0, 128, tid); CP_COMMIT();

    const int lo16 = lane & 15, hi2 = lane >> 4;
    uint32_t abase[4], bbase[4];
#pragma unroll
    for (int im = 0; im < 4; im++) abase[im] = (wm + im * 16 + lo16) * 128 + hi2 * 16;
#pragma unroll
    for (int in2 = 0; in2 < 4; in2++) bbase[in2] = lo16 * 256 + (wn + in2 * 16 + hi2 * 8) * 2;

    int st = 0;
    for (int kt = 0; kt < KT; kt++) {
        CP_WAIT2();
        __syncthreads();
        int ls = kt + 3;
        if (ls < KT) load_stage(sb, (st + 3) & 3, A, lda, B, ldb, m0, n0, ls * 64, tid);
        CP_COMMIT();
        const uint32_t sa = sb + st * STG, sbb = sa + 32768;
        uint32_t af[2][4][4], bfr[2][4][4];
#pragma unroll
        for (int im = 0; im < 4; im++) ldm4(af[0][im], sa + SWZA(abase[im]));
#pragma unroll
        for (int in2 = 0; in2 < 4; in2++) ldm4t(bfr[0][in2], sbb + SWZB(bbase[in2]));
#pragma unroll
        for (int kk = 0; kk < 4; kk++) {
            const int cur = kk & 1, nxt = cur ^ 1;
            if (kk < 3) {
#pragma unroll
                for (int im = 0; im < 4; im++) ldm4(af[nxt][im], sa + SWZA(abase[im] + (kk + 1) * 32));
#pragma unroll
                for (int in2 = 0; in2 < 4; in2++) ldm4t(bfr[nxt][in2], sbb + SWZB(bbase[in2] + (kk + 1) * 4096));
            }
#pragma unroll
            for (int im = 0; im < 4; im++)
#pragma unroll
                for (int in2 = 0; in2 < 4; in2++) {
                    mma16816(c[im][in2 * 2],     af[cur][im], bfr[cur][in2][0], bfr[cur][in2][1]);
                    mma16816(c[im][in2 * 2 + 1], af[cur][im], bfr[cur][in2][2], bfr[cur][in2][3]);
                }
        }
        st = (st + 1) & 3;
    }
    __syncthreads();

    // stage accumulators -> smem (256 x 129 floats)
    float* stf = (float*)smem;
    const int rin = lane >> 2, cp2 = (lane & 3) * 2;
#pragma unroll
    for (int im = 0; im < 4; im++)
#pragma unroll
        for (int i8 = 0; i8 < 8; i8++) {
            int rr = wm + im * 16 + rin, cc = wn + i8 * 8 + cp2;
            stf[rr * 129 + cc]           = c[im][i8][0];
            stf[rr * 129 + cc + 1]       = c[im][i8][1];
            stf[(rr + 8) * 129 + cc]     = c[im][i8][2];
            stf[(rr + 8) * 129 + cc + 1] = c[im][i8][3];
        }
    __syncthreads();

#pragma unroll 4
    for (int i = 0; i < 128; i++) {
        const int idx = tid + i * 256;
        int r, cc;
        if (EPI == 1 || EPI == 2 || EPI == 5) { r = idx & 255; cc = idx >> 8; }
        else { r = idx >> 7; cc = idx & 127; }
        float v = stf[r * 129 + cc];
        const int row2 = m0 + r, col = n0 + cc;
        if (EPI == 0) {
            if (col < 4096) {
                v += __ldg(bias + col);
                int h = col >> 9, d = col & 511;
                fp16 hi, lo; split2(v, hi, lo);
                size_t base = ((size_t)h * 2048 + row2) * 1536 + d;
                g_Q3[base] = hi; g_Q3[base + 512] = lo; g_Q3[base + 1024] = hi;
            } else {
                Cf[(size_t)row2 * 512 + (col - 4096)] = v;   // xp
            }
        } else if (EPI == 1) {
            v += __ldg(bias + col);
            int h = col >> 9, d = col & 511;
            int b = row2 >> 10, t = row2 & 1023;
            fp16 hi, lo; split2(v, hi, lo);
            size_t base = (size_t)(h * 2 + b) * 1536 * 1024 + (size_t)d * 1024 + t;
            g_K3T[base] = hi; g_K3T[base + 512 * 1024] = hi; g_K3T[base + 1024 * 1024] = lo;
        } else if (EPI == 2) {
            v += __ldg(bias + col);
            int h = col >> 9, d = col & 511;
            int b = row2 >> 10, s = row2 & 1023;
            g_V1T[(size_t)(h * 2 + b) * 512 * 1024 + (size_t)d * 1024 + s] = __float2half(v);
        } else if (EPI == 4) {
            g_E[(size_t)z * 1048576 + (size_t)row2 * 1024 + col] = g_mask[col] ? v : NEG_INF;
        } else {  // EPI == 5: tile rows = d (M=512), cols = t
            const int h = z >> 1, b = z & 1;
            const int d = row2, t = col;
            float g = __ldg(gamma + h);
            float xp = __ldg(XP + ((size_t)b * 1024 + t) * 512 + d);
            Cf[(((size_t)(b * 8 + h)) * 1024 + t) * 512 + d] = (g * v + xp) * (1.0f / (g + 1.0f));
        }
    }
}

// ---------------- aux ----------------
__global__ void normalize_mask_kernel(const unsigned char* __restrict__ raw, int n) {
    __shared__ int s_c0, s_chi;
    if (threadIdx.x == 0) { s_c0 = 0; s_chi = 0; }
    __syncthreads();
    int c0 = 0, chi = 0;
    for (int t = threadIdx.x; t < 256; t += blockDim.x) {
        unsigned char b0 = raw[4*t], b1 = raw[4*t+1], b2 = raw[4*t+2], b3 = raw[4*t+3];
        if (b0) c0++;
        if (b1 | b2 | b3) chi++;
    }
    atomicAdd(&s_c0, c0); atomicAdd(&s_chi, chi);
    __syncthreads();
    int mode = (s_chi == 0) ? 1 : (s_c0 == 0 ? 2 : 0);
    for (int t = threadIdx.x; t < n; t += blockDim.x) {
        int v;
        if (mode == 0) v = (raw[t] != 0);
        else if (mode == 1) v = (((const int*)raw)[t] != 0);
        else v = (((const float*)raw)[t] != 0.0f);
        g_mask[t] = v;
    }
}

__global__ void splitX(const float* __restrict__ in, fp16* __restrict__ out) {
    int i = blockIdx.x * 256 + threadIdx.x;
    int m = i >> 9, k = i & 511;
    fp16 h, l; split2(in[i], h, l);
    size_t base = (size_t)m * 1536 + k;
    out[base] = h; out[base + 512] = l; out[base + 1024] = h;
}

// W [512][Nin] -> triple rows [Wh;Wh;Wl] into out with row-stride ldout at column col0
__global__ void splitW_str(const float* __restrict__ in, fp16* __restrict__ out,
                           int Nin, int ldout, int col0, int n) {
    int i = blockIdx.x * 256 + threadIdx.x;
    if (i < n) {
        int r = i / Nin, cc = i - r * Nin;
        fp16 h, l; split2(in[i], h, l);
        size_t o = (size_t)r * ldout + col0 + cc;
        out[o] = h;
        out[o + (size_t)512 * ldout] = h;
        out[o + (size_t)1024 * ldout] = l;
    }
}

__global__ void splitWhi(const float* __restrict__ in, fp16* __restrict__ out, int n) {
    int i = blockIdx.x * 256 + threadIdx.x;
    if (i < n) out[i] = __float2half(in[i]);
}

// softmax over rows of g_E; writes fp16 attn to g_AF
__global__ void softmax_kernel(void) {
    const size_t row = blockIdx.x;
    const float* p = g_E + row * SSZ;
    fp16* q = g_AF + row * SSZ;
    const int t = threadIdx.x;
    float4 v = reinterpret_cast<const float4*>(p)[t];
    float mx = fmaxf(fmaxf(v.x, v.y), fmaxf(v.z, v.w));
    __shared__ float red[8]; __shared__ float s_max, s_sum;
#pragma unroll
    for (int o = 16; o > 0; o >>= 1) mx = fmaxf(mx, __shfl_xor_sync(~0u, mx, o));
    if ((t & 31) == 0) red[t >> 5] = mx;
    __syncthreads();
    if (t == 0) { float m = red[0]; for (int i = 1; i < 8; i++) m = fmaxf(m, red[i]); s_max = m; }
    __syncthreads();
    const float m = s_max;
    float4 e = {__expf(v.x-m), __expf(v.y-m), __expf(v.z-m), __expf(v.w-m)};
    float s = e.x + e.y + e.z + e.w;
#pragma unroll
    for (int o = 16; o > 0; o >>= 1) s += __shfl_xor_sync(~0u, s, o);
    if ((t & 31) == 0) red[t >> 5] = s;
    __syncthreads();
    if (t == 0) { float ss = 0.f; for (int i = 0; i < 8; i++) ss += red[i]; s_sum = ss; }
    __syncthreads();
    const float inv = 1.0f / s_sum;
    __half2* q2 = reinterpret_cast<__half2*>(q);
    q2[2 * t]     = __floats2half2_rn(e.x * inv, e.y * inv);
    q2[2 * t + 1] = __floats2half2_rn(e.z * inv, e.w * inv);
}

// ---------------- launch ----------------
template<int EPI>
static void launch_gemm(dim3 grid, const fp16* A, int lda, const fp16* B, int ldb, int K,
                        size_t Az, size_t Bz, const float* bias, float* Cf,
                        const float* gamma, const float* XP) {
    cudaFuncSetAttribute(gemm_mma<EPI>, cudaFuncAttributeMaxDynamicSharedMemorySize, SMTOT);
    gemm_mma<EPI><<<grid, 256, SMTOT>>>(A, lda, B, ldb, K, Az, Bz, bias, Cf, gamma, XP);
}

extern "C" void kernel_launch(void* const* d_in, const int* in_sizes, int n_in,
                              void* d_out, int out_size)
{
    const float* x = (const float*)d_in[0];
    const float* y = (const float*)d_in[1];
    const float* Wq = (const float*)d_in[2];
    const float* bq = (const float*)d_in[3];
    const float* Wk = (const float*)d_in[4];
    const float* bk = (const float*)d_in[5];
    const float* Wv = (const float*)d_in[6];
    const float* bv = (const float*)d_in[7];
    const float* Wp = (const float*)d_in[8];
    const float* gamma = (const float*)d_in[9];
    const unsigned char* mask_raw = (const unsigned char*)d_in[10];
    float* out = (float*)d_out;

    fp16 *x3, *y3, *W3qp, *W3k, *Wvh, *Q3, *K3T, *V1T, *AF;
    float *XP;
    cudaGetSymbolAddress((void**)&x3, g_x3);     cudaGetSymbolAddress((void**)&y3, g_y3);
    cudaGetSymbolAddress((void**)&W3qp, g_W3qp); cudaGetSymbolAddress((void**)&W3k, g_W3k);
    cudaGetSymbolAddress((void**)&Wvh, g_Wvh);   cudaGetSymbolAddress((void**)&Q3, g_Q3);
    cudaGetSymbolAddress((void**)&K3T, g_K3T);   cudaGetSymbolAddress((void**)&V1T, g_V1T);
    cudaGetSymbolAddress((void**)&AF, g_AF);     cudaGetSymbolAddress((void**)&XP, g_XP);

    normalize_mask_kernel<<<1, 256>>>(mask_raw, SSZ);
    splitX<<<4096, 256>>>(x, x3);
    splitX<<<4096, 256>>>(y, y3);
    splitW_str<<<8192, 256>>>(Wq, W3qp, 4096, 4608, 0, 512 * 4096);
    splitW_str<<<1024, 256>>>(Wp, W3qp, 512, 4608, 4096, 512 * 512);
    splitW_str<<<8192, 256>>>(Wk, W3k, 4096, 4096, 0, 512 * 4096);
    splitWhi<<<8192, 256>>>(Wv, Wvh, 512 * 4096);

    // Q proj + xp: M=2048, N=4608, K=1536 (3-pass)
    launch_gemm<0>(dim3(36, 8, 1), x3, 1536, W3qp, 4608, 1536, 0, 0, bq, XP, nullptr, nullptr);
    // K proj: M=2048, N=4096, K=1536 (3-pass), transposed store
    launch_gemm<1>(dim3(32, 8, 1), y3, 1536, W3k, 4096, 1536, 0, 0, bk, nullptr, nullptr, nullptr);
    // V proj: 1-pass fp16, transposed fp16 store
    launch_gemm<2>(dim3(32, 8, 1), y3, 1536, Wvh, 4096, 512, 0, 0, bv, nullptr, nullptr, nullptr);
    // energy per hb: M=N=1024, K=1536 (3-pass)
    launch_gemm<4>(dim3(8, 4, 16), Q3, 1536, K3T, 1024, 1536,
                   (size_t)1024 * 1536, (size_t)1536 * 1024, nullptr, nullptr, nullptr, nullptr);
    softmax_kernel<<<16384, 256>>>();
    // out per hb: M=512 (d), N=1024 (t), K=1024 (s): Vt * attn
    launch_gemm<5>(dim3(8, 2, 16), V1T, 1024, AF, 1024, 1024,
                   (size_t)512 * 1024, (size_t)1024 * 1024, nullptr, out, gamma, XP);
}

// round 7
// speedup vs baseline: 2.7791x; 1.0389x over previous
#include <cuda_runtime.h>
#include <cuda_fp16.h>
#include <cstdint>

#define SSZ 1024
#define NEG_INF -1e30f
typedef __half fp16;

// ---------------- scratch ----------------
__device__ __align__(256) fp16  g_x3[2048*1536];              // [m][ xh | xl | xh ]
__device__ __align__(256) fp16  g_y3[2048*1536];
__device__ __align__(256) fp16  g_W3qp[1536*4608];            // [Wq3 | Wp3] packed, ld 4608
__device__ __align__(256) fp16  g_W3k[1536*4096];
__device__ __align__(256) fp16  g_Wvh[512*4096];              // hi-only
__device__ __align__(256) fp16  g_Q3 [16*1024*1536];          // [h][2048 rows][ Qh | Ql | Qh ]
__device__ __align__(256) fp16  g_K3T[16*1536*1024];          // [hb][ Kh ; Kh ; Kl ][t]
__device__ __align__(256) fp16  g_V1T[16*512*1024];           // [hb][d][s] fp16
__device__ __align__(256) float g_E  [(size_t)16*1024*1024];  // [hb][s][t] f32
__device__ __align__(256) fp16  g_AF [(size_t)16*1024*1024];  // [hb][s][t] fp16 attn
__device__ __align__(256) float g_XP [2048*512];
__device__ int g_mask[SSZ];

// ---------------- helpers ----------------
__device__ __forceinline__ uint32_t smem_u32(const void* p) {
    uint32_t a;
    asm("{ .reg .u64 t; cvta.to.shared.u64 t, %1; cvt.u32.u64 %0, t; }" : "=r"(a) : "l"(p));
    return a;
}
#define SWZA(x) ((x) ^ (((x) >> 3) & 0x70))   // 128B rows
#define SWZB(x) ((x) ^ (((x) >> 4) & 0x70))   // 256B rows
__device__ __forceinline__ void cp16(uint32_t dst, const void* src) {
    asm volatile("cp.async.cg.shared.global [%0], [%1], 16;" :: "r"(dst), "l"(src));
}
#define CP_COMMIT() asm volatile("cp.async.commit_group;" ::: "memory")
#define CP_WAIT1()  asm volatile("cp.async.wait_group 1;" ::: "memory")
__device__ __forceinline__ void ldm4(uint32_t* d, uint32_t a) {
    asm volatile("ldmatrix.sync.aligned.m8n8.x4.shared.b16 {%0,%1,%2,%3}, [%4];"
                 : "=r"(d[0]), "=r"(d[1]), "=r"(d[2]), "=r"(d[3]) : "r"(a));
}
__device__ __forceinline__ void ldm4t(uint32_t* d, uint32_t a) {
    asm volatile("ldmatrix.sync.aligned.m8n8.x4.trans.shared.b16 {%0,%1,%2,%3}, [%4];"
                 : "=r"(d[0]), "=r"(d[1]), "=r"(d[2]), "=r"(d[3]) : "r"(a));
}
__device__ __forceinline__ void mma16816(float* c, const uint32_t* a, uint32_t b0, uint32_t b1) {
    asm volatile("mma.sync.aligned.m16n8k16.row.col.f32.f16.f16.f32 "
                 "{%0,%1,%2,%3}, {%4,%5,%6,%7}, {%8,%9}, {%0,%1,%2,%3};"
                 : "+f"(c[0]), "+f"(c[1]), "+f"(c[2]), "+f"(c[3])
                 : "r"(a[0]), "r"(a[1]), "r"(a[2]), "r"(a[3]), "r"(b0), "r"(b1));
}
__device__ __forceinline__ void split2(float v, fp16& h, fp16& l) {
    h = __float2half(v);
    l = __float2half(v - __half2float(h));
}

// ---------------- GEMM: CTA 128x128, 128 thr (4 warps of 64x64), 3 stages -> 2 CTA/SM ----
#define STG 32768
#define SMTOT (3*STG)

__device__ __forceinline__ void load_stage(uint32_t sb, int st, const fp16* A, int lda,
                                           const fp16* B, int ldb, int m0, int n0, int k0, int tid) {
    uint32_t sa = sb + st * STG, sbb = sa + 16384;
    const fp16* Ab = A + (size_t)m0 * lda + k0;
    const fp16* Bb = B + (size_t)k0 * ldb + n0;
#pragma unroll
    for (int i = 0; i < 8; i++) {
        int idx = tid + i * 128, r = idx >> 3, c = idx & 7;
        cp16(sa + SWZA(r * 128 + c * 16), Ab + (size_t)r * lda + c * 8);
    }
#pragma unroll
    for (int i = 0; i < 8; i++) {
        int idx = tid + i * 128, kr = idx >> 4, c = idx & 15;
        cp16(sbb + SWZB(kr * 256 + c * 16), Bb + (size_t)kr * ldb + c * 8);
    }
}

// EPI: 0=Q proj + xp (N=4608), 1=K proj(transposed), 2=V proj(transposed fp16),
//      4=energy+mask, 5=out blend (tile is [d][t])
template<int EPI>
__global__ void __launch_bounds__(128, 2)
gemm_mma(const fp16* __restrict__ A, int lda, const fp16* __restrict__ B, int ldb, int K,
         size_t Az, size_t Bz, const float* __restrict__ bias, float* __restrict__ Cf,
         const float* __restrict__ gamma, const float* __restrict__ XP)
{
    extern __shared__ char smem[];
    const uint32_t sb = smem_u32(smem);
    const int tid = threadIdx.x, wid = tid >> 5, lane = tid & 31;
    const int wm = (wid & 1) * 64, wn = (wid >> 1) * 64;
    const int m0 = blockIdx.y * 128, n0 = blockIdx.x * 128, z = blockIdx.z;
    A += (size_t)z * Az; B += (size_t)z * Bz;

    float c[4][8][4];
#pragma unroll
    for (int i = 0; i < 4; i++)
#pragma unroll
        for (int j = 0; j < 8; j++)
#pragma unroll
            for (int q = 0; q < 4; q++) c[i][j][q] = 0.f;

    const int KT = K / 64;
    load_stage(sb, 0, A, lda, B, ldb, m0, n0, 0, tid); CP_COMMIT();
    load_stage(sb, 1, A, lda, B, ldb, m0, n0, 64, tid); CP_COMMIT();

    const int lo16 = lane & 15, hi2 = lane >> 4;
    uint32_t abase[4], bbase[4];
#pragma unroll
    for (int im = 0; im < 4; im++) abase[im] = (wm + im * 16 + lo16) * 128 + hi2 * 16;
#pragma unroll
    for (int in2 = 0; in2 < 4; in2++) bbase[in2] = lo16 * 256 + (wn + in2 * 16 + hi2 * 8) * 2;

    int st = 0;
    for (int kt = 0; kt < KT; kt++) {
        CP_WAIT1();
        __syncthreads();
        int ls = kt + 2;
        if (ls < KT) {
            int st2 = st + 2; if (st2 >= 3) st2 -= 3;
            load_stage(sb, st2, A, lda, B, ldb, m0, n0, ls * 64, tid);
        }
        CP_COMMIT();
        const uint32_t sa = sb + st * STG, sbb = sa + 16384;
        uint32_t af[2][4][4], bfr[2][4][4];
#pragma unroll
        for (int im = 0; im < 4; im++) ldm4(af[0][im], sa + SWZA(abase[im]));
#pragma unroll
        for (int in2 = 0; in2 < 4; in2++) ldm4t(bfr[0][in2], sbb + SWZB(bbase[in2]));
#pragma unroll
        for (int kk = 0; kk < 4; kk++) {
            const int cur = kk & 1, nxt = cur ^ 1;
            if (kk < 3) {
#pragma unroll
                for (int im = 0; im < 4; im++) ldm4(af[nxt][im], sa + SWZA(abase[im] + (kk + 1) * 32));
#pragma unroll
                for (int in2 = 0; in2 < 4; in2++) ldm4t(bfr[nxt][in2], sbb + SWZB(bbase[in2] + (kk + 1) * 4096));
            }
#pragma unroll
            for (int im = 0; im < 4; im++)
#pragma unroll
                for (int in2 = 0; in2 < 4; in2++) {
                    mma16816(c[im][in2 * 2],     af[cur][im], bfr[cur][in2][0], bfr[cur][in2][1]);
                    mma16816(c[im][in2 * 2 + 1], af[cur][im], bfr[cur][in2][2], bfr[cur][in2][3]);
                }
        }
        st++; if (st == 3) st = 0;
    }
    __syncthreads();

    // stage accumulators -> smem (128 x 129 floats = 66KB <= 96KB)
    float* stf = (float*)smem;
    const int rin = lane >> 2, cp2 = (lane & 3) * 2;
#pragma unroll
    for (int im = 0; im < 4; im++)
#pragma unroll
        for (int i8 = 0; i8 < 8; i8++) {
            int rr = wm + im * 16 + rin, cc = wn + i8 * 8 + cp2;
            stf[rr * 129 + cc]           = c[im][i8][0];
            stf[rr * 129 + cc + 1]       = c[im][i8][1];
            stf[(rr + 8) * 129 + cc]     = c[im][i8][2];
            stf[(rr + 8) * 129 + cc + 1] = c[im][i8][3];
        }
    __syncthreads();

#pragma unroll 4
    for (int i = 0; i < 128; i++) {
        const int idx = tid + i * 128;
        int r, cc;
        if (EPI == 1 || EPI == 2 || EPI == 5) { r = idx & 127; cc = idx >> 7; }
        else { r = idx >> 7; cc = idx & 127; }
        float v = stf[r * 129 + cc];
        const int row2 = m0 + r, col = n0 + cc;
        if (EPI == 0) {
            if (col < 4096) {
                v += __ldg(bias + col);
                int h = col >> 9, d = col & 511;
                fp16 hi, lo; split2(v, hi, lo);
                size_t base = ((size_t)h * 2048 + row2) * 1536 + d;
                g_Q3[base] = hi; g_Q3[base + 512] = lo; g_Q3[base + 1024] = hi;
            } else {
                Cf[(size_t)row2 * 512 + (col - 4096)] = v;   // xp
            }
        } else if (EPI == 1) {
            v += __ldg(bias + col);
            int h = col >> 9, d = col & 511;
            int b = row2 >> 10, t = row2 & 1023;
            fp16 hi, lo; split2(v, hi, lo);
            size_t base = (size_t)(h * 2 + b) * 1536 * 1024 + (size_t)d * 1024 + t;
            g_K3T[base] = hi; g_K3T[base + 512 * 1024] = hi; g_K3T[base + 1024 * 1024] = lo;
        } else if (EPI == 2) {
            v += __ldg(bias + col);
            int h = col >> 9, d = col & 511;
            int b = row2 >> 10, s = row2 & 1023;
            g_V1T[(size_t)(h * 2 + b) * 512 * 1024 + (size_t)d * 1024 + s] = __float2half(v);
        } else if (EPI == 4) {
            g_E[(size_t)z * 1048576 + (size_t)row2 * 1024 + col] = g_mask[col] ? v : NEG_INF;
        } else {  // EPI == 5: tile rows = d (M=512), cols = t
            const int h = z >> 1, b = z & 1;
            const int d = row2, t = col;
            float g = __ldg(gamma + h);
            float xp = __ldg(XP + ((size_t)b * 1024 + t) * 512 + d);
            Cf[(((size_t)(b * 8 + h)) * 1024 + t) * 512 + d] = (g * v + xp) * (1.0f / (g + 1.0f));
        }
    }
}

// ---------------- aux ----------------
__global__ void normalize_mask_kernel(const unsigned char* __restrict__ raw, int n) {
    __shared__ int s_c0, s_chi;
    if (threadIdx.x == 0) { s_c0 = 0; s_chi = 0; }
    __syncthreads();
    int c0 = 0, chi = 0;
    for (int t = threadIdx.x; t < 256; t += blockDim.x) {
        unsigned char b0 = raw[4*t], b1 = raw[4*t+1], b2 = raw[4*t+2], b3 = raw[4*t+3];
        if (b0) c0++;
        if (b1 | b2 | b3) chi++;
    }
    atomicAdd(&s_c0, c0); atomicAdd(&s_chi, chi);
    __syncthreads();
    int mode = (s_chi == 0) ? 1 : (s_c0 == 0 ? 2 : 0);
    for (int t = threadIdx.x; t < n; t += blockDim.x) {
        int v;
        if (mode == 0) v = (raw[t] != 0);
        else if (mode == 1) v = (((const int*)raw)[t] != 0);
        else v = (((const float*)raw)[t] != 0.0f);
        g_mask[t] = v;
    }
}

__global__ void splitX(const float* __restrict__ in, fp16* __restrict__ out) {
    int i = blockIdx.x * 256 + threadIdx.x;
    int m = i >> 9, k = i & 511;
    fp16 h, l; split2(in[i], h, l);
    size_t base = (size_t)m * 1536 + k;
    out[base] = h; out[base + 512] = l; out[base + 1024] = h;
}

__global__ void splitW_str(const float* __restrict__ in, fp16* __restrict__ out,
                           int Nin, int ldout, int col0, int n) {
    int i = blockIdx.x * 256 + threadIdx.x;
    if (i < n) {
        int r = i / Nin, cc = i - r * Nin;
        fp16 h, l; split2(in[i], h, l);
        size_t o = (size_t)r * ldout + col0 + cc;
        out[o] = h;
        out[o + (size_t)512 * ldout] = h;
        out[o + (size_t)1024 * ldout] = l;
    }
}

__global__ void splitWhi(const float* __restrict__ in, fp16* __restrict__ out, int n) {
    int i = blockIdx.x * 256 + threadIdx.x;
    if (i < n) out[i] = __float2half(in[i]);
}

__global__ void softmax_kernel(void) {
    const size_t row = blockIdx.x;
    const float* p = g_E + row * SSZ;
    fp16* q = g_AF + row * SSZ;
    const int t = threadIdx.x;
    float4 v = reinterpret_cast<const float4*>(p)[t];
    float mx = fmaxf(fmaxf(v.x, v.y), fmaxf(v.z, v.w));
    __shared__ float red[8]; __shared__ float s_max, s_sum;
#pragma unroll
    for (int o = 16; o > 0; o >>= 1) mx = fmaxf(mx, __shfl_xor_sync(~0u, mx, o));
    if ((t & 31) == 0) red[t >> 5] = mx;
    __syncthreads();
    if (t == 0) { float m = red[0]; for (int i = 1; i < 8; i++) m = fmaxf(m, red[i]); s_max = m; }
    __syncthreads();
    const float m = s_max;
    float4 e = {__expf(v.x-m), __expf(v.y-m), __expf(v.z-m), __expf(v.w-m)};
    float s = e.x + e.y + e.z + e.w;
#pragma unroll
    for (int o = 16; o > 0; o >>= 1) s += __shfl_xor_sync(~0u, s, o);
    if ((t & 31) == 0) red[t >> 5] = s;
    __syncthreads();
    if (t == 0) { float ss = 0.f; for (int i = 0; i < 8; i++) ss += red[i]; s_sum = ss; }
    __syncthreads();
    const float inv = 1.0f / s_sum;
    __half2* q2 = reinterpret_cast<__half2*>(q);
    q2[2 * t]     = __floats2half2_rn(e.x * inv, e.y * inv);
    q2[2 * t + 1] = __floats2half2_rn(e.z * inv, e.w * inv);
}

// ---------------- launch ----------------
template<int EPI>
static void launch_gemm(dim3 grid, const fp16* A, int lda, const fp16* B, int ldb, int K,
                        size_t Az, size_t Bz, const float* bias, float* Cf,
                        const float* gamma, const float* XP) {
    cudaFuncSetAttribute(gemm_mma<EPI>, cudaFuncAttributeMaxDynamicSharedMemorySize, SMTOT);
    gemm_mma<EPI><<<grid, 128, SMTOT>>>(A, lda, B, ldb, K, Az, Bz, bias, Cf, gamma, XP);
}

extern "C" void kernel_launch(void* const* d_in, const int* in_sizes, int n_in,
                              void* d_out, int out_size)
{
    const float* x = (const float*)d_in[0];
    const float* y = (const float*)d_in[1];
    const float* Wq = (const float*)d_in[2];
    const float* bq = (const float*)d_in[3];
    const float* Wk = (const float*)d_in[4];
    const float* bk = (const float*)d_in[5];
    const float* Wv = (const float*)d_in[6];
    const float* bv = (const float*)d_in[7];
    const float* Wp = (const float*)d_in[8];
    const float* gamma = (const float*)d_in[9];
    const unsigned char* mask_raw = (const unsigned char*)d_in[10];
    float* out = (float*)d_out;

    fp16 *x3, *y3, *W3qp, *W3k, *Wvh, *Q3, *K3T, *V1T, *AF;
    float *XP;
    cudaGetSymbolAddress((void**)&x3, g_x3);     cudaGetSymbolAddress((void**)&y3, g_y3);
    cudaGetSymbolAddress((void**)&W3qp, g_W3qp); cudaGetSymbolAddress((void**)&W3k, g_W3k);
    cudaGetSymbolAddress((void**)&Wvh, g_Wvh);   cudaGetSymbolAddress((void**)&Q3, g_Q3);
    cudaGetSymbolAddress((void**)&K3T, g_K3T);   cudaGetSymbolAddress((void**)&V1T, g_V1T);
    cudaGetSymbolAddress((void**)&AF, g_AF);     cudaGetSymbolAddress((void**)&XP, g_XP);

    // launches 0-4: prep. launch 5: Q-proj GEMM (ncu profiles launch #5).
    splitX<<<4096, 256>>>(x, x3);
    splitX<<<4096, 256>>>(y, y3);
    splitW_str<<<8192, 256>>>(Wq, W3qp, 4096, 4608, 0, 512 * 4096);
    splitW_str<<<1024, 256>>>(Wp, W3qp, 512, 4608, 4096, 512 * 512);
    splitW_str<<<8192, 256>>>(Wk, W3k, 4096, 4096, 0, 512 * 4096);

    // Q proj + xp: M=2048, N=4608, K=1536 (3-pass)
    launch_gemm<0>(dim3(36, 16, 1), x3, 1536, W3qp, 4608, 1536, 0, 0, bq, XP, nullptr, nullptr);

    splitWhi<<<8192, 256>>>(Wv, Wvh, 512 * 4096);
    // K proj: M=2048, N=4096, K=1536 (3-pass), transposed store
    launch_gemm<1>(dim3(32, 16, 1), y3, 1536, W3k, 4096, 1536, 0, 0, bk, nullptr, nullptr, nullptr);
    // V proj: 1-pass fp16, transposed fp16 store
    launch_gemm<2>(dim3(32, 16, 1), y3, 1536, Wvh, 4096, 512, 0, 0, bv, nullptr, nullptr, nullptr);
    normalize_mask_kernel<<<1, 256>>>(mask_raw, SSZ);
    // energy per hb: M=N=1024, K=1536 (3-pass)
    launch_gemm<4>(dim3(8, 8, 16), Q3, 1536, K3T, 1024, 1536,
                   (size_t)1024 * 1536, (size_t)1536 * 1024, nullptr, nullptr, nullptr, nullptr);
    softmax_kernel<<<16384, 256>>>();
    // out per hb: M=512 (d), N=1024 (t), K=1024 (s): Vt * attn
    launch_gemm<5>(dim3(8, 4, 16), V1T, 1024, AF, 1024, 1024,
                   (size_t)512 * 1024, (size_t)1024 * 1024, nullptr, out, gamma, XP);
}

// round 8
// speedup vs baseline: 3.1080x; 1.1183x over previous
#include <cuda_runtime.h>
#include <cuda_fp16.h>
#include <cstdint>

#define SSZ 1024
#define NEG_INF -1e30f
typedef __half fp16;

// ---------------- scratch ----------------
__device__ __align__(256) fp16  g_x3[2048*1536];              // [m][ xh | xl | xh ]
__device__ __align__(256) fp16  g_y3[2048*1536];
__device__ __align__(256) fp16  g_W3qp[1536*4608];            // [Wq3 | Wp3] packed, ld 4608
__device__ __align__(256) fp16  g_W3k[1536*4096];
__device__ __align__(256) fp16  g_Wvh[512*4096];              // hi-only
__device__ __align__(256) fp16  g_Q3 [16*1024*1536];          // [h][2048 rows][ Qh | Ql | Qh ]
__device__ __align__(256) fp16  g_K3T[16*1536*1024];          // [hb][ Kh ; Kh ; Kl ][t]
__device__ __align__(256) fp16  g_V1T[16*512*1024];           // [hb][d][s] fp16
__device__ __align__(256) float g_E  [(size_t)16*1024*1024];  // [hb][s][t] f32
__device__ __align__(256) fp16  g_AF [(size_t)16*1024*1024];  // [hb][s][t] fp16 attn
__device__ __align__(256) float g_XP [2048*512];
__device__ int g_mask[SSZ];

// ---------------- helpers ----------------
__device__ __forceinline__ uint32_t smem_u32(const void* p) {
    uint32_t a;
    asm("{ .reg .u64 t; cvta.to.shared.u64 t, %1; cvt.u32.u64 %0, t; }" : "=r"(a) : "l"(p));
    return a;
}
#define SWZA(x) ((x) ^ (((x) >> 3) & 0x70))   // 128B rows
#define SWZB(x) ((x) ^ (((x) >> 4) & 0x70))   // 256B rows
__device__ __forceinline__ void cp16(uint32_t dst, const void* src) {
    asm volatile("cp.async.cg.shared.global [%0], [%1], 16;" :: "r"(dst), "l"(src));
}
#define CP_COMMIT() asm volatile("cp.async.commit_group;" ::: "memory")
#define CP_WAIT1()  asm volatile("cp.async.wait_group 1;" ::: "memory")
__device__ __forceinline__ void ldm4(uint32_t* d, uint32_t a) {
    asm volatile("ldmatrix.sync.aligned.m8n8.x4.shared.b16 {%0,%1,%2,%3}, [%4];"
                 : "=r"(d[0]), "=r"(d[1]), "=r"(d[2]), "=r"(d[3]) : "r"(a));
}
__device__ __forceinline__ void ldm4t(uint32_t* d, uint32_t a) {
    asm volatile("ldmatrix.sync.aligned.m8n8.x4.trans.shared.b16 {%0,%1,%2,%3}, [%4];"
                 : "=r"(d[0]), "=r"(d[1]), "=r"(d[2]), "=r"(d[3]) : "r"(a));
}
__device__ __forceinline__ void mma16816(float* c, const uint32_t* a, uint32_t b0, uint32_t b1) {
    asm volatile("mma.sync.aligned.m16n8k16.row.col.f32.f16.f16.f32 "
                 "{%0,%1,%2,%3}, {%4,%5,%6,%7}, {%8,%9}, {%0,%1,%2,%3};"
                 : "+f"(c[0]), "+f"(c[1]), "+f"(c[2]), "+f"(c[3])
                 : "r"(a[0]), "r"(a[1]), "r"(a[2]), "r"(a[3]), "r"(b0), "r"(b1));
}
__device__ __forceinline__ void split2(float v, fp16& h, fp16& l) {
    h = __float2half(v);
    l = __float2half(v - __half2float(h));
}

// ---------------- GEMM: CTA 128x128, 256 thr (8 warps of 64x32), 3 stages, 2 CTA/SM ----
#define STG 32768
#define SMTOT (3*STG)

__device__ __forceinline__ void load_stage(uint32_t sb, int st, const fp16* A, int lda,
                                           const fp16* B, int ldb, int m0, int n0, int k0, int tid) {
    uint32_t sa = sb + st * STG, sbb = sa + 16384;
    const fp16* Ab = A + (size_t)m0 * lda + k0;
    const fp16* Bb = B + (size_t)k0 * ldb + n0;
#pragma unroll
    for (int i = 0; i < 4; i++) {
        int idx = tid + i * 256, r = idx >> 3, c = idx & 7;
        cp16(sa + SWZA(r * 128 + c * 16), Ab + (size_t)r * lda + c * 8);
    }
#pragma unroll
    for (int i = 0; i < 4; i++) {
        int idx = tid + i * 256, kr = idx >> 4, c = idx & 15;
        cp16(sbb + SWZB(kr * 256 + c * 16), Bb + (size_t)kr * ldb + c * 8);
    }
}

// EPI: 0=Q proj + xp (N=4608), 1=K proj(transposed), 2=V proj(transposed fp16),
//      4=energy+mask, 5=out blend (tile is [d][t])
template<int EPI>
__global__ void __launch_bounds__(256, 2)
gemm_mma(const fp16* __restrict__ A, int lda, const fp16* __restrict__ B, int ldb, int K,
         size_t Az, size_t Bz, const float* __restrict__ bias, float* __restrict__ Cf,
         const float* __restrict__ gamma, const float* __restrict__ XP)
{
    extern __shared__ char smem[];
    const uint32_t sb = smem_u32(smem);
    const int tid = threadIdx.x, wid = tid >> 5, lane = tid & 31;
    const int wm = (wid & 1) * 64, wn = (wid >> 1) * 32;
    const int m0 = blockIdx.y * 128, n0 = blockIdx.x * 128, z = blockIdx.z;
    A += (size_t)z * Az; B += (size_t)z * Bz;

    float c[4][4][4];
#pragma unroll
    for (int i = 0; i < 4; i++)
#pragma unroll
        for (int j = 0; j < 4; j++)
#pragma unroll
            for (int q = 0; q < 4; q++) c[i][j][q] = 0.f;

    const int KT = K / 64;
    load_stage(sb, 0, A, lda, B, ldb, m0, n0, 0, tid); CP_COMMIT();
    load_stage(sb, 1, A, lda, B, ldb, m0, n0, 64, tid); CP_COMMIT();

    const int lo16 = lane & 15, hi2 = lane >> 4;
    uint32_t abase[4], bbase[2];
#pragma unroll
    for (int im = 0; im < 4; im++) abase[im] = (wm + im * 16 + lo16) * 128 + hi2 * 16;
#pragma unroll
    for (int in2 = 0; in2 < 2; in2++) bbase[in2] = lo16 * 256 + (wn + in2 * 16 + hi2 * 8) * 2;

    int st = 0;
    for (int kt = 0; kt < KT; kt++) {
        CP_WAIT1();
        __syncthreads();
        int ls = kt + 2;
        if (ls < KT) {
            int st2 = st + 2; if (st2 >= 3) st2 -= 3;
            load_stage(sb, st2, A, lda, B, ldb, m0, n0, ls * 64, tid);
        }
        CP_COMMIT();
        const uint32_t sa = sb + st * STG, sbb = sa + 16384;
        uint32_t af[2][4][4], bfr[2][2][4];
#pragma unroll
        for (int im = 0; im < 4; im++) ldm4(af[0][im], sa + SWZA(abase[im]));
#pragma unroll
        for (int in2 = 0; in2 < 2; in2++) ldm4t(bfr[0][in2], sbb + SWZB(bbase[in2]));
#pragma unroll
        for (int kk = 0; kk < 4; kk++) {
            const int cur = kk & 1, nxt = cur ^ 1;
            if (kk < 3) {
#pragma unroll
                for (int im = 0; im < 4; im++) ldm4(af[nxt][im], sa + SWZA(abase[im] + (kk + 1) * 32));
#pragma unroll
                for (int in2 = 0; in2 < 2; in2++) ldm4t(bfr[nxt][in2], sbb + SWZB(bbase[in2] + (kk + 1) * 4096));
            }
#pragma unroll
            for (int im = 0; im < 4; im++)
#pragma unroll
                for (int in2 = 0; in2 < 2; in2++) {
                    mma16816(c[im][in2 * 2],     af[cur][im], bfr[cur][in2][0], bfr[cur][in2][1]);
                    mma16816(c[im][in2 * 2 + 1], af[cur][im], bfr[cur][in2][2], bfr[cur][in2][3]);
                }
        }
        st++; if (st == 3) st = 0;
    }
    __syncthreads();

    // stage accumulators -> smem (128 x 129 floats = 66KB <= 96KB)
    float* stf = (float*)smem;
    const int rin = lane >> 2, cp2 = (lane & 3) * 2;
#pragma unroll
    for (int im = 0; im < 4; im++)
#pragma unroll
        for (int i8 = 0; i8 < 4; i8++) {
            int rr = wm + im * 16 + rin, cc = wn + i8 * 8 + cp2;
            stf[rr * 129 + cc]           = c[im][i8][0];
            stf[rr * 129 + cc + 1]       = c[im][i8][1];
            stf[(rr + 8) * 129 + cc]     = c[im][i8][2];
            stf[(rr + 8) * 129 + cc + 1] = c[im][i8][3];
        }
    __syncthreads();

#pragma unroll 4
    for (int i = 0; i < 64; i++) {
        const int idx = tid + i * 256;
        int r, cc;
        if (EPI == 1 || EPI == 2 || EPI == 5) { r = idx & 127; cc = idx >> 7; }
        else { r = idx >> 7; cc = idx & 127; }
        float v = stf[r * 129 + cc];
        const int row2 = m0 + r, col = n0 + cc;
        if (EPI == 0) {
            if (col < 4096) {
                v += __ldg(bias + col);
                int h = col >> 9, d = col & 511;
                fp16 hi, lo; split2(v, hi, lo);
                size_t base = ((size_t)h * 2048 + row2) * 1536 + d;
                g_Q3[base] = hi; g_Q3[base + 512] = lo; g_Q3[base + 1024] = hi;
            } else {
                Cf[(size_t)row2 * 512 + (col - 4096)] = v;   // xp
            }
        } else if (EPI == 1) {
            v += __ldg(bias + col);
            int h = col >> 9, d = col & 511;
            int b = row2 >> 10, t = row2 & 1023;
            fp16 hi, lo; split2(v, hi, lo);
            size_t base = (size_t)(h * 2 + b) * 1536 * 1024 + (size_t)d * 1024 + t;
            g_K3T[base] = hi; g_K3T[base + 512 * 1024] = hi; g_K3T[base + 1024 * 1024] = lo;
        } else if (EPI == 2) {
            v += __ldg(bias + col);
            int h = col >> 9, d = col & 511;
            int b = row2 >> 10, s = row2 & 1023;
            g_V1T[(size_t)(h * 2 + b) * 512 * 1024 + (size_t)d * 1024 + s] = __float2half(v);
        } else if (EPI == 4) {
            g_E[(size_t)z * 1048576 + (size_t)row2 * 1024 + col] = g_mask[col] ? v : NEG_INF;
        } else {  // EPI == 5: tile rows = d (M=512), cols = t
            const int h = z >> 1, b = z & 1;
            const int d = row2, t = col;
            float g = __ldg(gamma + h);
            float xp = __ldg(XP + ((size_t)b * 1024 + t) * 512 + d);
            Cf[(((size_t)(b * 8 + h)) * 1024 + t) * 512 + d] = (g * v + xp) * (1.0f / (g + 1.0f));
        }
    }
}

// ---------------- aux ----------------
__global__ void normalize_mask_kernel(const unsigned char* __restrict__ raw, int n) {
    __shared__ int s_c0, s_chi;
    if (threadIdx.x == 0) { s_c0 = 0; s_chi = 0; }
    __syncthreads();
    int c0 = 0, chi = 0;
    for (int t = threadIdx.x; t < 256; t += blockDim.x) {
        unsigned char b0 = raw[4*t], b1 = raw[4*t+1], b2 = raw[4*t+2], b3 = raw[4*t+3];
        if (b0) c0++;
        if (b1 | b2 | b3) chi++;
    }
    atomicAdd(&s_c0, c0); atomicAdd(&s_chi, chi);
    __syncthreads();
    int mode = (s_chi == 0) ? 1 : (s_c0 == 0 ? 2 : 0);
    for (int t = threadIdx.x; t < n; t += blockDim.x) {
        int v;
        if (mode == 0) v = (raw[t] != 0);
        else if (mode == 1) v = (((const int*)raw)[t] != 0);
        else v = (((const float*)raw)[t] != 0.0f);
        g_mask[t] = v;
    }
}

__global__ void splitX(const float* __restrict__ in, fp16* __restrict__ out) {
    int i = blockIdx.x * 256 + threadIdx.x;
    int m = i >> 9, k = i & 511;
    fp16 h, l; split2(in[i], h, l);
    size_t base = (size_t)m * 1536 + k;
    out[base] = h; out[base + 512] = l; out[base + 1024] = h;
}

__global__ void splitW_str(const float* __restrict__ in, fp16* __restrict__ out,
                           int Nin, int ldout, int col0, int n) {
    int i = blockIdx.x * 256 + threadIdx.x;
    if (i < n) {
        int r = i / Nin, cc = i - r * Nin;
        fp16 h, l; split2(in[i], h, l);
        size_t o = (size_t)r * ldout + col0 + cc;
        out[o] = h;
        out[o + (size_t)512 * ldout] = h;
        out[o + (size_t)1024 * ldout] = l;
    }
}

__global__ void splitWhi(const float* __restrict__ in, fp16* __restrict__ out, int n) {
    int i = blockIdx.x * 256 + threadIdx.x;
    if (i < n) out[i] = __float2half(in[i]);
}

__global__ void softmax_kernel(void) {
    const size_t row = blockIdx.x;
    const float* p = g_E + row * SSZ;
    fp16* q = g_AF + row * SSZ;
    const int t = threadIdx.x;
    float4 v = reinterpret_cast<const float4*>(p)[t];
    float mx = fmaxf(fmaxf(v.x, v.y), fmaxf(v.z, v.w));
    __shared__ float red[8]; __shared__ float s_max, s_sum;
#pragma unroll
    for (int o = 16; o > 0; o >>= 1) mx = fmaxf(mx, __shfl_xor_sync(~0u, mx, o));
    if ((t & 31) == 0) red[t >> 5] = mx;
    __syncthreads();
    if (t == 0) { float m = red[0]; for (int i = 1; i < 8; i++) m = fmaxf(m, red[i]); s_max = m; }
    __syncthreads();
    const float m = s_max;
    float4 e = {__expf(v.x-m), __expf(v.y-m), __expf(v.z-m), __expf(v.w-m)};
    float s = e.x + e.y + e.z + e.w;
#pragma unroll
    for (int o = 16; o > 0; o >>= 1) s += __shfl_xor_sync(~0u, s, o);
    if ((t & 31) == 0) red[t >> 5] = s;
    __syncthreads();
    if (t == 0) { float ss = 0.f; for (int i = 0; i < 8; i++) ss += red[i]; s_sum = ss; }
    __syncthreads();
    const float inv = 1.0f / s_sum;
    __half2* q2 = reinterpret_cast<__half2*>(q);
    q2[2 * t]     = __floats2half2_rn(e.x * inv, e.y * inv);
    q2[2 * t + 1] = __floats2half2_rn(e.z * inv, e.w * inv);
}

// ---------------- launch ----------------
template<int EPI>
static void launch_gemm(dim3 grid, const fp16* A, int lda, const fp16* B, int ldb, int K,
                        size_t Az, size_t Bz, const float* bias, float* Cf,
                        const float* gamma, const float* XP) {
    cudaFuncSetAttribute(gemm_mma<EPI>, cudaFuncAttributeMaxDynamicSharedMemorySize, SMTOT);
    gemm_mma<EPI><<<grid, 256, SMTOT>>>(A, lda, B, ldb, K, Az, Bz, bias, Cf, gamma, XP);
}

extern "C" void kernel_launch(void* const* d_in, const int* in_sizes, int n_in,
                              void* d_out, int out_size)
{
    const float* x = (const float*)d_in[0];
    const float* y = (const float*)d_in[1];
    const float* Wq = (const float*)d_in[2];
    const float* bq = (const float*)d_in[3];
    const float* Wk = (const float*)d_in[4];
    const float* bk = (const float*)d_in[5];
    const float* Wv = (const float*)d_in[6];
    const float* bv = (const float*)d_in[7];
    const float* Wp = (const float*)d_in[8];
    const float* gamma = (const float*)d_in[9];
    const unsigned char* mask_raw = (const unsigned char*)d_in[10];
    float* out = (float*)d_out;

    fp16 *x3, *y3, *W3qp, *W3k, *Wvh, *Q3, *K3T, *V1T, *AF;
    float *XP;
    cudaGetSymbolAddress((void**)&x3, g_x3);     cudaGetSymbolAddress((void**)&y3, g_y3);
    cudaGetSymbolAddress((void**)&W3qp, g_W3qp); cudaGetSymbolAddress((void**)&W3k, g_W3k);
    cudaGetSymbolAddress((void**)&Wvh, g_Wvh);   cudaGetSymbolAddress((void**)&Q3, g_Q3);
    cudaGetSymbolAddress((void**)&K3T, g_K3T);   cudaGetSymbolAddress((void**)&V1T, g_V1T);
    cudaGetSymbolAddress((void**)&AF, g_AF);     cudaGetSymbolAddress((void**)&XP, g_XP);

    // launches 1-3: minimal prep for gemm<0>; launch 4 = gemm<0> (ncu captures launch #4)
    splitX<<<4096, 256>>>(x, x3);
    splitW_str<<<8192, 256>>>(Wq, W3qp, 4096, 4608, 0, 512 * 4096);
    splitW_str<<<1024, 256>>>(Wp, W3qp, 512, 4608, 4096, 512 * 512);

    // Q proj + xp: M=2048, N=4608, K=1536 (3-pass)  <-- profiled launch
    launch_gemm<0>(dim3(36, 16, 1), x3, 1536, W3qp, 4608, 1536, 0, 0, bq, XP, nullptr, nullptr);

    splitX<<<4096, 256>>>(y, y3);
    splitW_str<<<8192, 256>>>(Wk, W3k, 4096, 4096, 0, 512 * 4096);
    splitWhi<<<8192, 256>>>(Wv, Wvh, 512 * 4096);
    // K proj: M=2048, N=4096, K=1536 (3-pass), transposed store
    launch_gemm<1>(dim3(32, 16, 1), y3, 1536, W3k, 4096, 1536, 0, 0, bk, nullptr, nullptr, nullptr);
    // V proj: 1-pass fp16, transposed fp16 store
    launch_gemm<2>(dim3(32, 16, 1), y3, 1536, Wvh, 4096, 512, 0, 0, bv, nullptr, nullptr, nullptr);
    normalize_mask_kernel<<<1, 256>>>(mask_raw, SSZ);
    // energy per hb: M=N=1024, K=1536 (3-pass)
    launch_gemm<4>(dim3(8, 8, 16), Q3, 1536, K3T, 1024, 1536,
                   (size_t)1024 * 1536, (size_t)1536 * 1024, nullptr, nullptr, nullptr, nullptr);
    softmax_kernel<<<16384, 256>>>();
    // out per hb: M=512 (d), N=1024 (t), K=1024 (s): Vt * attn
    launch_gemm<5>(dim3(8, 4, 16), V1T, 1024, AF, 1024, 1024,
                   (size_t)512 * 1024, (size_t)1024 * 1024, nullptr, out, gamma, XP);
}

// round 9
// speedup vs baseline: 3.5758x; 1.1505x over previous
#include <cuda_runtime.h>
#include <cuda_fp16.h>
#include <cstdint>

#define NEG_INF -1e30f
typedef __half fp16;

// ---------------- scratch (hi/lo stored once; no triplication) ----------------
__device__ __align__(256) fp16  g_xh[2048*512], g_xl[2048*512];
__device__ __align__(256) fp16  g_yh[2048*512], g_yl[2048*512];
__device__ __align__(256) fp16  g_Wqph[512*4608], g_Wqpl[512*4608];  // [Wq | Wp]
__device__ __align__(256) fp16  g_Wkh[512*4096],  g_Wkl[512*4096];
__device__ __align__(256) fp16  g_Wvh[512*4096];
__device__ __align__(256) fp16  g_Qh[16*1024*512], g_Ql[16*1024*512];   // [h][2048][512]
__device__ __align__(256) fp16  g_KTh[16*512*1024], g_KTl[16*512*1024]; // [hb][d][t]
__device__ __align__(256) fp16  g_V1T[16*512*1024];                     // [hb][d][s]
__device__ __align__(256) float g_E [(size_t)16*1024*1024];             // [hb][s][t]
__device__ __align__(256) fp16  g_AF[(size_t)16*1024*1024];             // [hb][s][t]
__device__ __align__(256) float g_XP[2048*512];
__device__ int g_mask[1024];

// ---------------- helpers ----------------
__device__ __forceinline__ uint32_t smem_u32(const void* p) {
    uint32_t a;
    asm("{ .reg .u64 t; cvta.to.shared.u64 t, %1; cvt.u32.u64 %0, t; }" : "=r"(a) : "l"(p));
    return a;
}
#define SWZA(x) ((x) ^ (((x) >> 3) & 0x70))
#define SWZB(x) ((x) ^ (((x) >> 4) & 0x70))
__device__ __forceinline__ void cp16(uint32_t dst, const void* src) {
    asm volatile("cp.async.cg.shared.global [%0], [%1], 16;" :: "r"(dst), "l"(src));
}
#define CP_COMMIT() asm volatile("cp.async.commit_group;" ::: "memory")
#define CP_WAIT1()  asm volatile("cp.async.wait_group 1;" ::: "memory")
__device__ __forceinline__ void ldm4(uint32_t* d, uint32_t a) {
    asm volatile("ldmatrix.sync.aligned.m8n8.x4.shared.b16 {%0,%1,%2,%3}, [%4];"
                 : "=r"(d[0]), "=r"(d[1]), "=r"(d[2]), "=r"(d[3]) : "r"(a));
}
__device__ __forceinline__ void ldm4t(uint32_t* d, uint32_t a) {
    asm volatile("ldmatrix.sync.aligned.m8n8.x4.trans.shared.b16 {%0,%1,%2,%3}, [%4];"
                 : "=r"(d[0]), "=r"(d[1]), "=r"(d[2]), "=r"(d[3]) : "r"(a));
}
__device__ __forceinline__ void mma16816(float* c, const uint32_t* a, uint32_t b0, uint32_t b1) {
    asm volatile("mma.sync.aligned.m16n8k16.row.col.f32.f16.f16.f32 "
                 "{%0,%1,%2,%3}, {%4,%5,%6,%7}, {%8,%9}, {%0,%1,%2,%3};"
                 : "+f"(c[0]), "+f"(c[1]), "+f"(c[2]), "+f"(c[3])
                 : "r"(a[0]), "r"(a[1]), "r"(a[2]), "r"(a[3]), "r"(b0), "r"(b1));
}
__device__ __forceinline__ void split2(float v, fp16& h, fp16& l) {
    h = __float2half(v);
    l = __float2half(v - __half2float(h));
}
__device__ __forceinline__ const fp16* pick(const fp16* p0, const fp16* p1, const fp16* p2, int s) {
    return s == 0 ? p0 : (s == 1 ? p1 : p2);
}

// ---------------- segmented GEMM core: CTA 128x128, 8 warps of 64x32, 3 stages ----
#define STG 32768
#define SMTOT (3*STG)

// c[4][4][4]; segments of size Kseg (lda == Kseg), total KT 64-deep ktiles
__device__ __forceinline__ void gemm_core(
    const fp16* A0, const fp16* A1, const fp16* A2,
    const fp16* B0, const fp16* B1, const fp16* B2,
    int KT, int ksh, int Kseg, int ldb, int m0, int n0,
    uint32_t sb, int tid, float c[4][4][4])
{
    const int wid = tid >> 5, lane = tid & 31;
    const int wm = (wid & 1) * 64, wn = (wid >> 1) * 32;

    auto ldst = [&](int st, int kt) {
        int seg = kt >> ksh, k0 = (kt - (seg << ksh)) << 6;
        const fp16* A = pick(A0, A1, A2, seg) + (size_t)m0 * Kseg + k0;
        const fp16* B = pick(B0, B1, B2, seg) + (size_t)k0 * ldb + n0;
        uint32_t sa = sb + st * STG, sbb = sa + 16384;
#pragma unroll
        for (int i = 0; i < 4; i++) {
            int idx = tid + i * 256, r = idx >> 3, cc = idx & 7;
            cp16(sa + SWZA(r * 128 + cc * 16), A + (size_t)r * Kseg + cc * 8);
        }
#pragma unroll
        for (int i = 0; i < 4; i++) {
            int idx = tid + i * 256, kr = idx >> 4, cc = idx & 15;
            cp16(sbb + SWZB(kr * 256 + cc * 16), B + (size_t)kr * ldb + cc * 8);
        }
    };

    ldst(0, 0); CP_COMMIT();
    ldst(1, 1); CP_COMMIT();

    const int lo16 = lane & 15, hi2 = lane >> 4;
    uint32_t abase[4], bbase[2];
#pragma unroll
    for (int im = 0; im < 4; im++) abase[im] = (wm + im * 16 + lo16) * 128 + hi2 * 16;
#pragma unroll
    for (int in2 = 0; in2 < 2; in2++) bbase[in2] = lo16 * 256 + (wn + in2 * 16 + hi2 * 8) * 2;

    int st = 0;
    for (int kt = 0; kt < KT; kt++) {
        CP_WAIT1();
        __syncthreads();
        int ls = kt + 2;
        if (ls < KT) {
            int st2 = st + 2; if (st2 >= 3) st2 -= 3;
            ldst(st2, ls);
        }
        CP_COMMIT();
        const uint32_t sa = sb + st * STG, sbb = sa + 16384;
        uint32_t af[2][4][4], bfr[2][2][4];
#pragma unroll
        for (int im = 0; im < 4; im++) ldm4(af[0][im], sa + SWZA(abase[im]));
#pragma unroll
        for (int in2 = 0; in2 < 2; in2++) ldm4t(bfr[0][in2], sbb + SWZB(bbase[in2]));
#pragma unroll
        for (int kk = 0; kk < 4; kk++) {
            const int cur = kk & 1, nxt = cur ^ 1;
            if (kk < 3) {
#pragma unroll
                for (int im = 0; im < 4; im++) ldm4(af[nxt][im], sa + SWZA(abase[im] + (kk + 1) * 32));
#pragma unroll
                for (int in2 = 0; in2 < 2; in2++) ldm4t(bfr[nxt][in2], sbb + SWZB(bbase[in2] + (kk + 1) * 4096));
            }
#pragma unroll
            for (int im = 0; im < 4; im++)
#pragma unroll
                for (int in2 = 0; in2 < 2; in2++) {
                    mma16816(c[im][in2 * 2],     af[cur][im], bfr[cur][in2][0], bfr[cur][in2][1]);
                    mma16816(c[im][in2 * 2 + 1], af[cur][im], bfr[cur][in2][2], bfr[cur][in2][3]);
                }
        }
        st++; if (st == 3) st = 0;
    }
    __syncthreads();
}

__device__ __forceinline__ void stage_acc(float* stf, int tid, float c[4][4][4]) {
    const int wid = tid >> 5, lane = tid & 31;
    const int wm = (wid & 1) * 64, wn = (wid >> 1) * 32;
    const int rin = lane >> 2, cp2 = (lane & 3) * 2;
#pragma unroll
    for (int im = 0; im < 4; im++)
#pragma unroll
        for (int i8 = 0; i8 < 4; i8++) {
            int rr = wm + im * 16 + rin, cc = wn + i8 * 8 + cp2;
            stf[rr * 129 + cc]           = c[im][i8][0];
            stf[rr * 129 + cc + 1]       = c[im][i8][1];
            stf[(rr + 8) * 129 + cc]     = c[im][i8][2];
            stf[(rr + 8) * 129 + cc + 1] = c[im][i8][3];
        }
    __syncthreads();
}

// ---------------- mega projection: z=0 Q+xp, z=1 K(T), z=2 V(T) ----------------
__global__ void __launch_bounds__(256, 2)
gemm_proj(const float* __restrict__ bq, const float* __restrict__ bk,
          const float* __restrict__ bv)
{
    extern __shared__ char smem[];
    const int z = blockIdx.z;
    const int xt = (z == 0) ? 36 : 32;
    if ((int)blockIdx.x >= xt) return;
    const uint32_t sb = smem_u32(smem);
    const int tid = threadIdx.x;
    const int m0 = blockIdx.y * 128, n0 = blockIdx.x * 128;

    float c[4][4][4];
#pragma unroll
    for (int i = 0; i < 4; i++)
#pragma unroll
        for (int j = 0; j < 4; j++)
#pragma unroll
            for (int q = 0; q < 4; q++) c[i][j][q] = 0.f;

    if (z == 0)
        gemm_core(g_xh, g_xh, g_xl, g_Wqph, g_Wqpl, g_Wqph, 24, 3, 512, 4608, m0, n0, sb, tid, c);
    else if (z == 1)
        gemm_core(g_yh, g_yh, g_yl, g_Wkh, g_Wkl, g_Wkh, 24, 3, 512, 4096, m0, n0, sb, tid, c);
    else
        gemm_core(g_yh, nullptr, nullptr, g_Wvh, nullptr, nullptr, 8, 3, 512, 4096, m0, n0, sb, tid, c);

    float* stf = (float*)smem;
    stage_acc(stf, tid, c);

#pragma unroll 4
    for (int i = 0; i < 64; i++) {
        const int idx = tid + i * 256;
        int r, cc;
        if (z == 0) { r = idx >> 7; cc = idx & 127; } else { r = idx & 127; cc = idx >> 7; }
        float v = stf[r * 129 + cc];
        const int row2 = m0 + r, col = n0 + cc;
        if (z == 0) {
            if (col < 4096) {
                v += __ldg(bq + col);
                int h = col >> 9, d = col & 511;
                fp16 hi, lo; split2(v, hi, lo);
                size_t base = ((size_t)h * 2048 + row2) * 512 + d;
                g_Qh[base] = hi; g_Ql[base] = lo;
            } else {
                g_XP[(size_t)row2 * 512 + (col - 4096)] = v;
            }
        } else if (z == 1) {
            v += __ldg(bk + col);
            int h = col >> 9, d = col & 511;
            int b = row2 >> 10, t = row2 & 1023;
            fp16 hi, lo; split2(v, hi, lo);
            size_t base = (size_t)(h * 2 + b) * 512 * 1024 + (size_t)d * 1024 + t;
            g_KTh[base] = hi; g_KTl[base] = lo;
        } else {
            v += __ldg(bv + col);
            int h = col >> 9, d = col & 511;
            int b = row2 >> 10, s = row2 & 1023;
            g_V1T[(size_t)(h * 2 + b) * 512 * 1024 + (size_t)d * 1024 + s] = __float2half(v);
        }
    }
}

// ---------------- energy: per hb, M=N=1024, segments (Qh,KTh),(Qh,KTl),(Ql,KTh) ----
__global__ void __launch_bounds__(256, 2)
gemm_energy(void)
{
    extern __shared__ char smem[];
    const uint32_t sb = smem_u32(smem);
    const int tid = threadIdx.x, z = blockIdx.z;
    const int m0 = blockIdx.y * 128, n0 = blockIdx.x * 128;
    const fp16* Ah = g_Qh + (size_t)z * 1024 * 512;
    const fp16* Al = g_Ql + (size_t)z * 1024 * 512;
    const fp16* Bh = g_KTh + (size_t)z * 512 * 1024;
    const fp16* Bl = g_KTl + (size_t)z * 512 * 1024;

    float c[4][4][4];
#pragma unroll
    for (int i = 0; i < 4; i++)
#pragma unroll
        for (int j = 0; j < 4; j++)
#pragma unroll
            for (int q = 0; q < 4; q++) c[i][j][q] = 0.f;

    gemm_core(Ah, Ah, Al, Bh, Bl, Bh, 24, 3, 512, 1024, m0, n0, sb, tid, c);

    float* stf = (float*)smem;
    stage_acc(stf, tid, c);

#pragma unroll 4
    for (int i = 0; i < 64; i++) {
        const int idx = tid + i * 256;
        const int r = idx >> 7, cc = idx & 127;
        const int row2 = m0 + r, col = n0 + cc;
        float v = stf[r * 129 + cc];
        g_E[(size_t)z * 1048576 + (size_t)row2 * 1024 + col] = g_mask[col] ? v : NEG_INF;
    }
}

// ---------------- out: per hb, M=512 (d), N=1024 (t), K=1024: V1T * AF ----------
__global__ void __launch_bounds__(256, 2)
gemm_out(const float* __restrict__ gamma, float* __restrict__ out)
{
    extern __shared__ char smem[];
    const uint32_t sb = smem_u32(smem);
    const int tid = threadIdx.x, z = blockIdx.z;
    const int m0 = blockIdx.y * 128, n0 = blockIdx.x * 128;
    const fp16* A0 = g_V1T + (size_t)z * 512 * 1024;
    const fp16* B0 = g_AF + (size_t)z * 1024 * 1024;

    float c[4][4][4];
#pragma unroll
    for (int i = 0; i < 4; i++)
#pragma unroll
        for (int j = 0; j < 4; j++)
#pragma unroll
            for (int q = 0; q < 4; q++) c[i][j][q] = 0.f;

    gemm_core(A0, nullptr, nullptr, B0, nullptr, nullptr, 16, 4, 1024, 1024, m0, n0, sb, tid, c);

    float* stf = (float*)smem;
    stage_acc(stf, tid, c);

    const int h = z >> 1, b = z & 1;
    const float g = __ldg(gamma + h);
    const float inv = 1.0f / (g + 1.0f);
#pragma unroll 4
    for (int i = 0; i < 64; i++) {
        const int idx = tid + i * 256;
        const int r = idx & 127, cc = idx >> 7;   // r: d (coalesced), cc: t
        const int d = m0 + r, t = n0 + cc;
        float v = stf[r * 129 + cc];
        float xp = __ldg(g_XP + ((size_t)b * 1024 + t) * 512 + d);
        out[(((size_t)(b * 8 + h)) * 1024 + t) * 512 + d] = (g * v + xp) * inv;
    }
}

// ---------------- aux ----------------
__global__ void normalize_mask_kernel(const unsigned char* __restrict__ raw, int n) {
    __shared__ int s_c0, s_chi;
    if (threadIdx.x == 0) { s_c0 = 0; s_chi = 0; }
    __syncthreads();
    int c0 = 0, chi = 0;
    for (int t = threadIdx.x; t < 256; t += blockDim.x) {
        unsigned char b0 = raw[4*t], b1 = raw[4*t+1], b2 = raw[4*t+2], b3 = raw[4*t+3];
        if (b0) c0++;
        if (b1 | b2 | b3) chi++;
    }
    atomicAdd(&s_c0, c0); atomicAdd(&s_chi, chi);
    __syncthreads();
    int mode = (s_chi == 0) ? 1 : (s_c0 == 0 ? 2 : 0);
    for (int t = threadIdx.x; t < n; t += blockDim.x) {
        int v;
        if (mode == 0) v = (raw[t] != 0);
        else if (mode == 1) v = (((const int*)raw)[t] != 0);
        else v = (((const float*)raw)[t] != 0.0f);
        g_mask[t] = v;
    }
}

__global__ void splitXY(const float* __restrict__ x, const float* __restrict__ y) {
    int i = blockIdx.x * 256 + threadIdx.x;          // 2 * 2^20 total
    int sel = i >> 20, j = i & 1048575;
    float v = sel ? y[j] : x[j];
    fp16 h, l; split2(v, h, l);
    if (sel) { g_yh[j] = h; g_yl[j] = l; } else { g_xh[j] = h; g_xl[j] = l; }
}

__global__ void splitWqp(const float* __restrict__ Wq, const float* __restrict__ Wp) {
    int i = blockIdx.x * 256 + threadIdx.x;          // 512*4608
    int r = i / 4608, cc = i - r * 4608;
    float v = (cc < 4096) ? Wq[(size_t)r * 4096 + cc] : Wp[(size_t)r * 512 + (cc - 4096)];
    fp16 h, l; split2(v, h, l);
    g_Wqph[i] = h; g_Wqpl[i] = l;
}

__global__ void splitWkv(const float* __restrict__ Wk, const float* __restrict__ Wv) {
    int i = blockIdx.x * 256 + threadIdx.x;          // 512*4096
    fp16 h, l; split2(Wk[i], h, l);
    g_Wkh[i] = h; g_Wkl[i] = l;
    g_Wvh[i] = __float2half(Wv[i]);
}

// warp-per-row softmax: block = 8 warps = 8 rows; reads g_E, writes fp16 g_AF
__global__ void softmax_kernel(void) {
    const int w = threadIdx.x >> 5, lane = threadIdx.x & 31;
    const size_t row = (size_t)blockIdx.x * 8 + w;
    const float4* p = reinterpret_cast<const float4*>(g_E + row * 1024);
    float4 v[8];
#pragma unroll
    for (int j = 0; j < 8; j++) v[j] = p[lane + 32 * j];
    float mx = -1e38f;
#pragma unroll
    for (int j = 0; j < 8; j++)
        mx = fmaxf(mx, fmaxf(fmaxf(v[j].x, v[j].y), fmaxf(v[j].z, v[j].w)));
#pragma unroll
    for (int o = 16; o > 0; o >>= 1) mx = fmaxf(mx, __shfl_xor_sync(~0u, mx, o));
    float s = 0.f;
#pragma unroll
    for (int j = 0; j < 8; j++) {
        v[j].x = __expf(v[j].x - mx); v[j].y = __expf(v[j].y - mx);
        v[j].z = __expf(v[j].z - mx); v[j].w = __expf(v[j].w - mx);
        s += v[j].x + v[j].y + v[j].z + v[j].w;
    }
#pragma unroll
    for (int o = 16; o > 0; o >>= 1) s += __shfl_xor_sync(~0u, s, o);
    const float inv = 1.0f / s;
    __half2* q = reinterpret_cast<__half2*>(g_AF + row * 1024);
#pragma unroll
    for (int j = 0; j < 8; j++) {
        q[2 * (lane + 32 * j)]     = __floats2half2_rn(v[j].x * inv, v[j].y * inv);
        q[2 * (lane + 32 * j) + 1] = __floats2half2_rn(v[j].z * inv, v[j].w * inv);
    }
}

// ---------------- launch ----------------
extern "C" void kernel_launch(void* const* d_in, const int* in_sizes, int n_in,
                              void* d_out, int out_size)
{
    const float* x = (const float*)d_in[0];
    const float* y = (const float*)d_in[1];
    const float* Wq = (const float*)d_in[2];
    const float* bq = (const float*)d_in[3];
    const float* Wk = (const float*)d_in[4];
    const float* bk = (const float*)d_in[5];
    const float* Wv = (const float*)d_in[6];
    const float* bv = (const float*)d_in[7];
    const float* Wp = (const float*)d_in[8];
    const float* gamma = (const float*)d_in[9];
    const unsigned char* mask_raw = (const unsigned char*)d_in[10];
    float* out = (float*)d_out;

    cudaFuncSetAttribute(gemm_proj,   cudaFuncAttributeMaxDynamicSharedMemorySize, SMTOT);
    cudaFuncSetAttribute(gemm_energy, cudaFuncAttributeMaxDynamicSharedMemorySize, SMTOT);
    cudaFuncSetAttribute(gemm_out,    cudaFuncAttributeMaxDynamicSharedMemorySize, SMTOT);

    // 1-3: prep; 4: mega projection GEMM (ncu captures launch #4)
    splitXY<<<8192, 256>>>(x, y);
    splitWqp<<<9216, 256>>>(Wq, Wp);
    splitWkv<<<8192, 256>>>(Wk, Wv);

    gemm_proj<<<dim3(36, 16, 3), 256, SMTOT>>>(bq, bk, bv);

    normalize_mask_kernel<<<1, 256>>>(mask_raw, 1024);
    gemm_energy<<<dim3(8, 8, 16), 256, SMTOT>>>();
    softmax_kernel<<<2048, 256>>>();
    gemm_out<<<dim3(8, 4, 16), 256, SMTOT>>>(gamma, out);
}

// round 10
// speedup vs baseline: 3.6485x; 1.0203x over previous
#include <cuda_runtime.h>
#include <cuda_fp16.h>
#include <cstdint>

#define NEG_INF -1e30f
typedef __half fp16;

// ---------------- scratch ----------------
__device__ __align__(256) fp16  g_xh[2048*512], g_xl[2048*512];
__device__ __align__(256) fp16  g_yh[2048*512], g_yl[2048*512];
__device__ __align__(256) fp16  g_Wqph[512*4608], g_Wqpl[512*4608];  // [Wq | Wp]
__device__ __align__(256) fp16  g_Wkh[512*4096],  g_Wkl[512*4096];
__device__ __align__(256) fp16  g_Wvh[512*4096];
__device__ __align__(256) fp16  g_Qh[16*1024*512], g_Ql[16*1024*512];   // [h][2048][512]
__device__ __align__(256) fp16  g_KTh[16*512*1024], g_KTl[16*512*1024]; // [hb][d][t]
__device__ __align__(256) fp16  g_V1T[16*512*1024];                     // [hb][d][s]
__device__ __align__(256) float g_E [(size_t)16*1024*1024];             // [hb][s][t]
__device__ __align__(256) fp16  g_AF[(size_t)16*1024*1024];             // [hb][s][t]
__device__ __align__(256) float g_XP[2048*512];
__device__ int g_mask[1024];

// ---------------- helpers ----------------
__device__ __forceinline__ uint32_t smem_u32(const void* p) {
    uint32_t a;
    asm("{ .reg .u64 t; cvta.to.shared.u64 t, %1; cvt.u32.u64 %0, t; }" : "=r"(a) : "l"(p));
    return a;
}
#define SWZA(x) ((x) ^ (((x) >> 3) & 0x70))
#define SWZB(x) ((x) ^ (((x) >> 4) & 0x70))
__device__ __forceinline__ void cp16(uint32_t dst, const void* src) {
    asm volatile("cp.async.cg.shared.global [%0], [%1], 16;" :: "r"(dst), "l"(src));
}
#define CP_COMMIT() asm volatile("cp.async.commit_group;" ::: "memory")
#define CP_WAIT1()  asm volatile("cp.async.wait_group 1;" ::: "memory")
__device__ __forceinline__ void ldm4(uint32_t* d, uint32_t a) {
    asm volatile("ldmatrix.sync.aligned.m8n8.x4.shared.b16 {%0,%1,%2,%3}, [%4];"
                 : "=r"(d[0]), "=r"(d[1]), "=r"(d[2]), "=r"(d[3]) : "r"(a));
}
__device__ __forceinline__ void ldm4t(uint32_t* d, uint32_t a) {
    asm volatile("ldmatrix.sync.aligned.m8n8.x4.trans.shared.b16 {%0,%1,%2,%3}, [%4];"
                 : "=r"(d[0]), "=r"(d[1]), "=r"(d[2]), "=r"(d[3]) : "r"(a));
}
__device__ __forceinline__ void mma16816(float* c, const uint32_t* a, uint32_t b0, uint32_t b1) {
    asm volatile("mma.sync.aligned.m16n8k16.row.col.f32.f16.f16.f32 "
                 "{%0,%1,%2,%3}, {%4,%5,%6,%7}, {%8,%9}, {%0,%1,%2,%3};"
                 : "+f"(c[0]), "+f"(c[1]), "+f"(c[2]), "+f"(c[3])
                 : "r"(a[0]), "r"(a[1]), "r"(a[2]), "r"(a[3]), "r"(b0), "r"(b1));
}
__device__ __forceinline__ void split2(float v, fp16& h, fp16& l) {
    h = __float2half(v);
    l = __float2half(v - __half2float(h));
}
__device__ __forceinline__ const fp16* pick(const fp16* p0, const fp16* p1, const fp16* p2, int s) {
    return s == 0 ? p0 : (s == 1 ? p1 : p2);
}

// ---------------- segmented GEMM core: CTA 128x128, 8 warps of 64x32, 3 stages ----
#define STG 32768
#define SMTOT (3*STG)

__device__ __forceinline__ void gemm_core(
    const fp16* A0, const fp16* A1, const fp16* A2,
    const fp16* B0, const fp16* B1, const fp16* B2,
    int KT, int ksh, int Kseg, int ldb, int m0, int n0,
    uint32_t sb, int tid, float c[4][4][4])
{
    const int wid = tid >> 5, lane = tid & 31;
    const int wm = (wid & 1) * 64, wn = (wid >> 1) * 32;

    // precomputed per-thread swizzled smem offsets (stage-relative)
    uint32_t saoff[4], sboff[4];
#pragma unroll
    for (int i = 0; i < 4; i++) {
        int idx = tid + i * 256;
        saoff[i] = SWZA((idx >> 3) * 128 + (idx & 7) * 16);
        sboff[i] = 16384 + SWZB((idx >> 4) * 256 + (idx & 15) * 16);
    }
    const int aRow = tid >> 3, aCol = (tid & 7) * 8;
    const int bRow = tid >> 4, bCol = (tid & 15) * 8;
    const size_t aStep = (size_t)32 * Kseg;      // rows per i-chunk
    const size_t bStep = (size_t)16 * ldb;
    const size_t bAdv  = (size_t)64 * ldb;       // per ktile
    const int msk = (1 << ksh) - 1;

    const fp16* pA = A0;
    const fp16* pB = B0;
    int load_kt = 0;
    auto ldst = [&](int st) {
        if ((load_kt & msk) == 0) {
            int seg = load_kt >> ksh;
            pA = pick(A0, A1, A2, seg) + (size_t)(m0 + aRow) * Kseg + aCol;
            pB = pick(B0, B1, B2, seg) + (size_t)bRow * ldb + n0 + bCol;
        }
        uint32_t sa = sb + st * STG;
#pragma unroll
        for (int i = 0; i < 4; i++) cp16(sa + saoff[i], pA + i * aStep);
#pragma unroll
        for (int i = 0; i < 4; i++) cp16(sa + sboff[i], pB + i * bStep);
        pA += 64; pB += bAdv;
        load_kt++;
    };

    ldst(0); CP_COMMIT();
    ldst(1); CP_COMMIT();

    const int lo16 = lane & 15, hi2 = lane >> 4;
    uint32_t abase[4], bbase[2];
#pragma unroll
    for (int im = 0; im < 4; im++) abase[im] = (wm + im * 16 + lo16) * 128 + hi2 * 16;
#pragma unroll
    for (int in2 = 0; in2 < 2; in2++) bbase[in2] = lo16 * 256 + (wn + in2 * 16 + hi2 * 8) * 2;

    int st = 0;
    for (int kt = 0; kt < KT; kt++) {
        CP_WAIT1();
        __syncthreads();
        if (kt + 2 < KT) {
            int st2 = st + 2; if (st2 >= 3) st2 -= 3;
            ldst(st2);
        }
        CP_COMMIT();
        const uint32_t sa = sb + st * STG, sbb = sa + 16384;
        uint32_t af[2][4][4], bfr[2][2][4];
#pragma unroll
        for (int im = 0; im < 4; im++) ldm4(af[0][im], sa + SWZA(abase[im]));
#pragma unroll
        for (int in2 = 0; in2 < 2; in2++) ldm4t(bfr[0][in2], sbb + SWZB(bbase[in2]));
#pragma unroll
        for (int kk = 0; kk < 4; kk++) {
            const int cur = kk & 1, nxt = cur ^ 1;
            if (kk < 3) {
#pragma unroll
                for (int im = 0; im < 4; im++) ldm4(af[nxt][im], sa + SWZA(abase[im] + (kk + 1) * 32));
#pragma unroll
                for (int in2 = 0; in2 < 2; in2++) ldm4t(bfr[nxt][in2], sbb + SWZB(bbase[in2] + (kk + 1) * 4096));
            }
#pragma unroll
            for (int im = 0; im < 4; im++)
#pragma unroll
                for (int in2 = 0; in2 < 2; in2++) {
                    mma16816(c[im][in2 * 2],     af[cur][im], bfr[cur][in2][0], bfr[cur][in2][1]);
                    mma16816(c[im][in2 * 2 + 1], af[cur][im], bfr[cur][in2][2], bfr[cur][in2][3]);
                }
        }
        st++; if (st == 3) st = 0;
    }
    __syncthreads();
}

__device__ __forceinline__ void stage_acc(float* stf, int tid, float c[4][4][4]) {
    const int wid = tid >> 5, lane = tid & 31;
    const int wm = (wid & 1) * 64, wn = (wid >> 1) * 32;
    const int rin = lane >> 2, cp2 = (lane & 3) * 2;
#pragma unroll
    for (int im = 0; im < 4; im++)
#pragma unroll
        for (int i8 = 0; i8 < 4; i8++) {
            int rr = wm + im * 16 + rin, cc = wn + i8 * 8 + cp2;
            stf[rr * 129 + cc]           = c[im][i8][0];
            stf[rr * 129 + cc + 1]       = c[im][i8][1];
            stf[(rr + 8) * 129 + cc]     = c[im][i8][2];
            stf[(rr + 8) * 129 + cc + 1] = c[im][i8][3];
        }
    __syncthreads();
}

// ---------------- mega projection: z=0 Q+xp, z=1 K(T), z=2 V(T) ----------------
__global__ void __launch_bounds__(256, 2)
gemm_proj(const float* __restrict__ bq, const float* __restrict__ bk,
          const float* __restrict__ bv)
{
    extern __shared__ char smem[];
    const int z = blockIdx.z;
    const int xt = (z == 0) ? 36 : 32;
    if ((int)blockIdx.x >= xt) return;
    const uint32_t sb = smem_u32(smem);
    const int tid = threadIdx.x;
    const int m0 = blockIdx.y * 128, n0 = blockIdx.x * 128;

    float c[4][4][4];
#pragma unroll
    for (int i = 0; i < 4; i++)
#pragma unroll
        for (int j = 0; j < 4; j++)
#pragma unroll
            for (int q = 0; q < 4; q++) c[i][j][q] = 0.f;

    if (z == 0)
        gemm_core(g_xh, g_xh, g_xl, g_Wqph, g_Wqpl, g_Wqph, 24, 3, 512, 4608, m0, n0, sb, tid, c);
    else if (z == 1)
        gemm_core(g_yh, g_yh, g_yl, g_Wkh, g_Wkl, g_Wkh, 24, 3, 512, 4096, m0, n0, sb, tid, c);
    else
        gemm_core(g_yh, nullptr, nullptr, g_Wvh, nullptr, nullptr, 8, 3, 512, 4096, m0, n0, sb, tid, c);

    float* stf = (float*)smem;
    stage_acc(stf, tid, c);

#pragma unroll 4
    for (int i = 0; i < 64; i++) {
        const int idx = tid + i * 256;
        int r, cc;
        if (z == 0) { r = idx >> 7; cc = idx & 127; } else { r = idx & 127; cc = idx >> 7; }
        float v = stf[r * 129 + cc];
        const int row2 = m0 + r, col = n0 + cc;
        if (z == 0) {
            if (col < 4096) {
                v += __ldg(bq + col);
                int h = col >> 9, d = col & 511;
                fp16 hi, lo; split2(v, hi, lo);
                size_t base = ((size_t)h * 2048 + row2) * 512 + d;
                g_Qh[base] = hi; g_Ql[base] = lo;
            } else {
                g_XP[(size_t)row2 * 512 + (col - 4096)] = v;
            }
        } else if (z == 1) {
            v += __ldg(bk + col);
            int h = col >> 9, d = col & 511;
            int b = row2 >> 10, t = row2 & 1023;
            fp16 hi, lo; split2(v, hi, lo);
            size_t base = (size_t)(h * 2 + b) * 512 * 1024 + (size_t)d * 1024 + t;
            g_KTh[base] = hi; g_KTl[base] = lo;
        } else {
            v += __ldg(bv + col);
            int h = col >> 9, d = col & 511;
            int b = row2 >> 10, s = row2 & 1023;
            g_V1T[(size_t)(h * 2 + b) * 512 * 1024 + (size_t)d * 1024 + s] = __float2half(v);
        }
    }
}

// ---------------- energy: per hb, M=N=1024, segments (Qh,KTh),(Qh,KTl),(Ql,KTh) ----
__global__ void __launch_bounds__(256, 2)
gemm_energy(void)
{
    extern __shared__ char smem[];
    const uint32_t sb = smem_u32(smem);
    const int tid = threadIdx.x, z = blockIdx.z;
    const int m0 = blockIdx.y * 128, n0 = blockIdx.x * 128;
    const fp16* Ah = g_Qh + (size_t)z * 1024 * 512;
    const fp16* Al = g_Ql + (size_t)z * 1024 * 512;
    const fp16* Bh = g_KTh + (size_t)z * 512 * 1024;
    const fp16* Bl = g_KTl + (size_t)z * 512 * 1024;

    float c[4][4][4];
#pragma unroll
    for (int i = 0; i < 4; i++)
#pragma unroll
        for (int j = 0; j < 4; j++)
#pragma unroll
            for (int q = 0; q < 4; q++) c[i][j][q] = 0.f;

    gemm_core(Ah, Ah, Al, Bh, Bl, Bh, 24, 3, 512, 1024, m0, n0, sb, tid, c);

    float* stf = (float*)smem;
    stage_acc(stf, tid, c);

#pragma unroll 4
    for (int i = 0; i < 64; i++) {
        const int idx = tid + i * 256;
        const int r = idx >> 7, cc = idx & 127;
        const int row2 = m0 + r, col = n0 + cc;
        float v = stf[r * 129 + cc];
        g_E[(size_t)z * 1048576 + (size_t)row2 * 1024 + col] = g_mask[col] ? v : NEG_INF;
    }
}

// ---------------- out: per hb, M=512 (d), N=1024 (t), K=1024: V1T * AF ----------
__global__ void __launch_bounds__(256, 2)
gemm_out(const float* __restrict__ gamma, float* __restrict__ out)
{
    extern __shared__ char smem[];
    const uint32_t sb = smem_u32(smem);
    const int tid = threadIdx.x, z = blockIdx.z;
    const int m0 = blockIdx.y * 128, n0 = blockIdx.x * 128;
    const fp16* A0 = g_V1T + (size_t)z * 512 * 1024;
    const fp16* B0 = g_AF + (size_t)z * 1024 * 1024;

    float c[4][4][4];
#pragma unroll
    for (int i = 0; i < 4; i++)
#pragma unroll
        for (int j = 0; j < 4; j++)
#pragma unroll
            for (int q = 0; q < 4; q++) c[i][j][q] = 0.f;

    gemm_core(A0, nullptr, nullptr, B0, nullptr, nullptr, 16, 4, 1024, 1024, m0, n0, sb, tid, c);

    float* stf = (float*)smem;
    stage_acc(stf, tid, c);

    const int h = z >> 1, b = z & 1;
    const float g = __ldg(gamma + h);
    const float inv = 1.0f / (g + 1.0f);
#pragma unroll 4
    for (int i = 0; i < 64; i++) {
        const int idx = tid + i * 256;
        const int r = idx & 127, cc = idx >> 7;   // r: d (coalesced), cc: t
        const int d = m0 + r, t = n0 + cc;
        float v = stf[r * 129 + cc];
        float xp = __ldg(g_XP + ((size_t)b * 1024 + t) * 512 + d);
        out[(((size_t)(b * 8 + h)) * 1024 + t) * 512 + d] = (g * v + xp) * inv;
    }
}

// ---------------- merged prep: blocks partitioned over 4 jobs ----------------
__global__ void prep_all(const float* __restrict__ x, const float* __restrict__ y,
                         const float* __restrict__ Wq, const float* __restrict__ Wp,
                         const float* __restrict__ Wk, const float* __restrict__ Wv)
{
    const int b = blockIdx.x, tid = threadIdx.x;
    if (b < 8192) {                          // split x,y
        int i = b * 256 + tid;
        int sel = i >> 20, j = i & 1048575;
        float v = sel ? y[j] : x[j];
        fp16 h, l; split2(v, h, l);
        if (sel) { g_yh[j] = h; g_yl[j] = l; } else { g_xh[j] = h; g_xl[j] = l; }
    } else if (b < 17408) {                  // Wq|Wp packed split
        int i = (b - 8192) * 256 + tid;
        int r = i / 4608, cc = i - r * 4608;
        float v = (cc < 4096) ? Wq[(size_t)r * 4096 + cc] : Wp[(size_t)r * 512 + (cc - 4096)];
        fp16 h, l; split2(v, h, l);
        g_Wqph[i] = h; g_Wqpl[i] = l;
    } else {                                 // Wk split + Wv hi
        int i = (b - 17408) * 256 + tid;
        fp16 h, l; split2(Wk[i], h, l);
        g_Wkh[i] = h; g_Wkl[i] = l;
        g_Wvh[i] = __float2half(Wv[i]);
    }
}

__global__ void normalize_mask_kernel(const unsigned char* __restrict__ raw, int n) {
    __shared__ int s_c0, s_chi;
    if (threadIdx.x == 0) { s_c0 = 0; s_chi = 0; }
    __syncthreads();
    int c0 = 0, chi = 0;
    for (int t = threadIdx.x; t < 256; t += blockDim.x) {
        unsigned char b0 = raw[4*t], b1 = raw[4*t+1], b2 = raw[4*t+2], b3 = raw[4*t+3];
        if (b0) c0++;
        if (b1 | b2 | b3) chi++;
    }
    atomicAdd(&s_c0, c0); atomicAdd(&s_chi, chi);
    __syncthreads();
    int mode = (s_chi == 0) ? 1 : (s_c0 == 0 ? 2 : 0);
    for (int t = threadIdx.x; t < n; t += blockDim.x) {
        int v;
        if (mode == 0) v = (raw[t] != 0);
        else if (mode == 1) v = (((const int*)raw)[t] != 0);
        else v = (((const float*)raw)[t] != 0.0f);
        g_mask[t] = v;
    }
}

// warp-per-row softmax: block = 8 warps = 8 rows
__global__ void softmax_kernel(void) {
    const int w = threadIdx.x >> 5, lane = threadIdx.x & 31;
    const size_t row = (size_t)blockIdx.x * 8 + w;
    const float4* p = reinterpret_cast<const float4*>(g_E + row * 1024);
    float4 v[8];
#pragma unroll
    for (int j = 0; j < 8; j++) v[j] = p[lane + 32 * j];
    float mx = -1e38f;
#pragma unroll
    for (int j = 0; j < 8; j++)
        mx = fmaxf(mx, fmaxf(fmaxf(v[j].x, v[j].y), fmaxf(v[j].z, v[j].w)));
#pragma unroll
    for (int o = 16; o > 0; o >>= 1) mx = fmaxf(mx, __shfl_xor_sync(~0u, mx, o));
    float s = 0.f;
#pragma unroll
    for (int j = 0; j < 8; j++) {
        v[j].x = __expf(v[j].x - mx); v[j].y = __expf(v[j].y - mx);
        v[j].z = __expf(v[j].z - mx); v[j].w = __expf(v[j].w - mx);
        s += v[j].x + v[j].y + v[j].z + v[j].w;
    }
#pragma unroll
    for (int o = 16; o > 0; o >>= 1) s += __shfl_xor_sync(~0u, s, o);
    const float inv = 1.0f / s;
    __half2* q = reinterpret_cast<__half2*>(g_AF + row * 1024);
#pragma unroll
    for (int j = 0; j < 8; j++) {
        q[2 * (lane + 32 * j)]     = __floats2half2_rn(v[j].x * inv, v[j].y * inv);
        q[2 * (lane + 32 * j) + 1] = __floats2half2_rn(v[j].z * inv, v[j].w * inv);
    }
}

// ---------------- launch ----------------
extern "C" void kernel_launch(void* const* d_in, const int* in_sizes, int n_in,
                              void* d_out, int out_size)
{
    const float* x = (const float*)d_in[0];
    const float* y = (const float*)d_in[1];
    const float* Wq = (const float*)d_in[2];
    const float* bq = (const float*)d_in[3];
    const float* Wk = (const float*)d_in[4];
    const float* bk = (const float*)d_in[5];
    const float* Wv = (const float*)d_in[6];
    const float* bv = (const float*)d_in[7];
    const float* Wp = (const float*)d_in[8];
    const float* gamma = (const float*)d_in[9];
    const unsigned char* mask_raw = (const unsigned char*)d_in[10];
    float* out = (float*)d_out;

    cudaFuncSetAttribute(gemm_proj,   cudaFuncAttributeMaxDynamicSharedMemorySize, SMTOT);
    cudaFuncSetAttribute(gemm_energy, cudaFuncAttributeMaxDynamicSharedMemorySize, SMTOT);
    cudaFuncSetAttribute(gemm_out,    cudaFuncAttributeMaxDynamicSharedMemorySize, SMTOT);

    // 1: prep, 2: proj, 3: mask, 4: energy (ncu captures launch #4), 5: softmax, 6: out
    prep_all<<<25600, 256>>>(x, y, Wq, Wp, Wk, Wv);
    gemm_proj<<<dim3(36, 16, 3), 256, SMTOT>>>(bq, bk, bv);
    normalize_mask_kernel<<<1, 256>>>(mask_raw, 1024);
    gemm_energy<<<dim3(8, 8, 16), 256, SMTOT>>>();
    softmax_kernel<<<2048, 256>>>();
    gemm_out<<<dim3(8, 4, 16), 256, SMTOT>>>(gamma, out);
}